// round 2
// baseline (speedup 1.0000x reference)
#include <cuda_runtime.h>
#include <cstdint>

#define BATCH 64
#define TCAP  32
#define VOCAB 32000
#define EDIM  1024
#define DDIM  1024
#define TDEC  31
#define NG    4096   // 4*DDIM

// ---------------- static scratch (no allocations allowed) ----------------
__device__ int   d_sortind[BATCH];
__device__ int   d_declen[BATCH];
__device__ int   d_cnt[TDEC];
__device__ int   d_i64;                                        // 1 if int inputs are int64
__device__ __align__(16) float d_X[TCAP * BATCH * EDIM];       // 8 MB   inputs per step
__device__ __align__(16) float d_gatesx[TCAP * BATCH * NG];    // 32 MB  x@W_ih^T + b_ih + b_hh
__device__ __align__(16) float d_hbuf[2][BATCH * DDIM];        // double-buffered h
__device__ __align__(16) float d_c[BATCH * DDIM];
__device__ __align__(16) float d_H[TDEC * BATCH * DDIM];       // 7.75 MB h-states

__device__ __forceinline__ float sigmf(float x) { return 1.0f / (1.0f + expf(-x)); }

// ---------------- setup: dtype sniff, stable argsort by -length, cnt prefix, tail outputs ----------------
__global__ void k_setup(const void* __restrict__ cap_len_raw,
                        float* __restrict__ out, int out_size)
{
    __shared__ int len[BATCH];
    const int* p32 = (const int*)cap_len_raw;
    // lengths are in [2,32], never 0. If int64 (little-endian), dword 1 is the
    // high half of element 0 -> 0. If int32, dword 1 is length[1] in [2,32] != 0.
    int is64 = (p32[1] == 0) ? 1 : 0;
    int i = threadIdx.x;
    if (i == 0) d_i64 = is64;
    if (i < BATCH) len[i] = p32[i << is64];
    __syncthreads();
    if (i < BATCH) {
        int li = len[i], r = 0;
        for (int j = 0; j < BATCH; j++) {
            int lj = len[j];
            if (lj > li || (lj == li && j < i)) r++;
        }
        d_sortind[r] = i;
        d_declen[r]  = li - 1;
    }
    __syncthreads();
    if (i < TDEC) {
        int c = 0;
        for (int b = 0; b < BATCH; b++)
            if (d_declen[b] > i) c++;
        d_cnt[i] = c;
    }
    __syncthreads();
    long long base = (long long)BATCH * TDEC * VOCAB;   // 63,488,000
    if (out_size >= (int)(base + 2 * BATCH) && i < BATCH) {
        out[base + i]          = (float)d_declen[i];
        out[base + BATCH + i]  = (float)d_sortind[i];
    }
}

// ---------------- gather: build X rows (t*64+b) ----------------
__global__ void __launch_bounds__(256) k_gather(const float* __restrict__ enc,
                                                const void* __restrict__ caps_raw,
                                                const float* __restrict__ emb)
{
    int row = blockIdx.x;          // t*BATCH + b
    int t = row >> 6, b = row & 63;
    int sb = d_sortind[b];
    const float* src;
    if (t == 0) {
        src = enc + (long long)sb * EDIM;
    } else {
        int idx = sb * TCAP + (t - 1);
        int is64 = d_i64;
        // low dword of a small non-negative int64 == the value (little-endian)
        int tok = ((const int*)caps_raw)[idx << is64];
        src = emb + (long long)tok * EDIM;
    }
    const float4* s4 = (const float4*)src;
    float4* dst = (float4*)(d_X + (long long)row * EDIM);
    dst[threadIdx.x] = s4[threadIdx.x];   // 256 threads * 4 floats = 1024
}

// ---------------- GEMM1: gatesx = X (2048x1024) @ W_ih^T (4096x1024) + b_ih + b_hh ----------------
__global__ void __launch_bounds__(256) k_gemm_inputs(const float* __restrict__ Wih,
                                                     const float* __restrict__ bih,
                                                     const float* __restrict__ bhh)
{
    __shared__ float As[16][64];
    __shared__ float Bs[16][64];
    int tid = threadIdx.x;
    int tx = tid & 15, ty = tid >> 4;
    int m0 = blockIdx.x * 64;      // x = M tile so consecutive blocks reuse W tile in L2
    int n0 = blockIdx.y * 64;
    int lr = tid >> 2, kq = (tid & 3) * 4;

    const float* Aptr = d_X + (long long)(m0 + lr) * EDIM + kq;
    const float* Bptr = Wih + (long long)(n0 + lr) * EDIM + kq;

    float acc[4][4] = {};
    for (int k0 = 0; k0 < EDIM; k0 += 16) {
        float4 a = *(const float4*)(Aptr + k0);
        float4 b = *(const float4*)(Bptr + k0);
        As[kq + 0][lr] = a.x; As[kq + 1][lr] = a.y; As[kq + 2][lr] = a.z; As[kq + 3][lr] = a.w;
        Bs[kq + 0][lr] = b.x; Bs[kq + 1][lr] = b.y; Bs[kq + 2][lr] = b.z; Bs[kq + 3][lr] = b.w;
        __syncthreads();
#pragma unroll
        for (int k = 0; k < 16; k++) {
            float4 av = *(const float4*)&As[k][ty * 4];
            float4 bv = *(const float4*)&Bs[k][tx * 4];
            float ar[4] = {av.x, av.y, av.z, av.w};
            float br[4] = {bv.x, bv.y, bv.z, bv.w};
#pragma unroll
            for (int i = 0; i < 4; i++)
#pragma unroll
                for (int j = 0; j < 4; j++)
                    acc[i][j] += ar[i] * br[j];
        }
        __syncthreads();
    }
#pragma unroll
    for (int i = 0; i < 4; i++) {
        int m = m0 + ty * 4 + i;
        int n = n0 + tx * 4;
        float4 v;
        v.x = acc[i][0] + bih[n + 0] + bhh[n + 0];
        v.y = acc[i][1] + bih[n + 1] + bhh[n + 1];
        v.z = acc[i][2] + bih[n + 2] + bhh[n + 2];
        v.w = acc[i][3] + bih[n + 3] + bhh[n + 3];
        *(float4*)&d_gatesx[(long long)m * NG + n] = v;
    }
}

// ---------------- step 0: initial cell, h=c=0 so gates = gatesx[t=0] ----------------
__global__ void __launch_bounds__(256) k_step0()
{
    int g = blockIdx.x * 256 + threadIdx.x;     // 0 .. 65535
    int b = g >> 10, d = g & 1023;
    const float* gx = d_gatesx + (long long)b * NG;
    float gi = gx[d];
    float gg = gx[2 * DDIM + d];
    float go = gx[3 * DDIM + d];
    float c = sigmf(gi) * tanhf(gg);            // f-term * c_old = 0
    float h = sigmf(go) * tanhf(c);
    d_c[g] = c;
    d_hbuf[0][g] = h;
}

// ---------------- recurrent step s (1..31): gates = gatesx[s] + h @ W_hh^T, pointwise+mask ----------------
__global__ void __launch_bounds__(256) k_step(int s, const float* __restrict__ Whh)
{
    __shared__ float Hs[16][64];
    __shared__ float Ws[16][32];
    __shared__ float Gs[64][32];

    int tid = threadIdx.x;
    int d0  = blockIdx.x * 8;                  // 8 hidden dims per block, grid 128
    int cnt = d_cnt[s - 1];
    int rp  = (s - 1) & 1, wp = s & 1;
    const float* hin  = d_hbuf[rp];
    float*       hout = d_hbuf[wp];

    int tx = tid & 15, ty = tid >> 4;          // cols tx*2 (+0,1), rows ty*4 (+0..3)
    int lrH = tid >> 2, kqH = (tid & 3) * 4;
    bool skip = (ty * 4 >= cnt);

    float acc[4][2] = {};
    for (int k0 = 0; k0 < DDIM; k0 += 16) {
        float4 hv = *(const float4*)(hin + (long long)lrH * DDIM + k0 + kqH);
        Hs[kqH + 0][lrH] = hv.x; Hs[kqH + 1][lrH] = hv.y;
        Hs[kqH + 2][lrH] = hv.z; Hs[kqH + 3][lrH] = hv.w;
        if (tid < 128) {
            int r = tid >> 2, kq = (tid & 3) * 4;
            int wrow = (r >> 3) * DDIM + d0 + (r & 7);
            float4 wv = *(const float4*)(Whh + (long long)wrow * DDIM + k0 + kq);
            Ws[kq + 0][r] = wv.x; Ws[kq + 1][r] = wv.y;
            Ws[kq + 2][r] = wv.z; Ws[kq + 3][r] = wv.w;
        }
        __syncthreads();
        if (!skip) {
#pragma unroll
            for (int k = 0; k < 16; k++) {
                float4 av = *(const float4*)&Hs[k][ty * 4];
                float2 bw = *(const float2*)&Ws[k][tx * 2];
                float ar[4] = {av.x, av.y, av.z, av.w};
#pragma unroll
                for (int i = 0; i < 4; i++) {
                    acc[i][0] += ar[i] * bw.x;
                    acc[i][1] += ar[i] * bw.y;
                }
            }
        }
        __syncthreads();
    }

    if (!skip) {
#pragma unroll
        for (int i = 0; i < 4; i++)
#pragma unroll
            for (int j = 0; j < 2; j++) {
                int row = ty * 4 + i;
                int col = tx * 2 + j;
                int gate = col >> 3, jj = col & 7;
                float v = acc[i][j] +
                    d_gatesx[((long long)s * BATCH + row) * NG + gate * DDIM + d0 + jj];
                Gs[row][col] = v;
            }
    }
    __syncthreads();

    // pointwise: 64 rows x 8 dims = 512 results, 2 per thread
    for (int it = tid; it < BATCH * 8; it += 256) {
        int b = it >> 3, j = it & 7;
        int hidx = b * DDIM + d0 + j;
        float hval;
        if (b < cnt) {
            float gi = Gs[b][j],      gf = Gs[b][8 + j];
            float gg = Gs[b][16 + j], go = Gs[b][24 + j];
            float cold = d_c[hidx];
            float cn = sigmf(gf) * cold + sigmf(gi) * tanhf(gg);
            float hn = sigmf(go) * tanhf(cn);
            d_c[hidx] = cn;
            hval = hn;
        } else {
            hval = hin[hidx];
        }
        hout[hidx] = hval;
        d_H[((long long)(s - 1) * BATCH + b) * DDIM + d0 + j] = hval;
    }
}

// ---------------- fc: preds[b][s][:] = mask ? H[s][b] @ fc_W^T + fc_b : 0 ----------------
__global__ void __launch_bounds__(256) k_fc(const float* __restrict__ fcW,
                                            const float* __restrict__ fcb,
                                            float* __restrict__ out)
{
    __shared__ float As[16][64];
    __shared__ float Bs[16][64];
    int s  = blockIdx.x;            // x = step so consecutive blocks reuse fcW tile in L2
    int n0 = blockIdx.y * 64;
    int cnt = d_cnt[s];
    int tid = threadIdx.x;
    int tx = tid & 15, ty = tid >> 4;
    int lr = tid >> 2, kq = (tid & 3) * 4;

    const float* Aptr = d_H + ((long long)s * BATCH + lr) * DDIM + kq;
    const float* Bptr = fcW + (long long)(n0 + lr) * DDIM + kq;
    bool skip = (ty * 4 >= cnt);

    float acc[4][4] = {};
    for (int k0 = 0; k0 < DDIM; k0 += 16) {
        float4 a = *(const float4*)(Aptr + k0);
        float4 b = *(const float4*)(Bptr + k0);
        As[kq + 0][lr] = a.x; As[kq + 1][lr] = a.y; As[kq + 2][lr] = a.z; As[kq + 3][lr] = a.w;
        Bs[kq + 0][lr] = b.x; Bs[kq + 1][lr] = b.y; Bs[kq + 2][lr] = b.z; Bs[kq + 3][lr] = b.w;
        __syncthreads();
        if (!skip) {
#pragma unroll
            for (int k = 0; k < 16; k++) {
                float4 av = *(const float4*)&As[k][ty * 4];
                float4 bv = *(const float4*)&Bs[k][tx * 4];
                float ar[4] = {av.x, av.y, av.z, av.w};
                float br[4] = {bv.x, bv.y, bv.z, bv.w};
#pragma unroll
                for (int i = 0; i < 4; i++)
#pragma unroll
                    for (int j = 0; j < 4; j++)
                        acc[i][j] += ar[i] * br[j];
            }
        }
        __syncthreads();
    }

    int n = n0 + tx * 4;
#pragma unroll
    for (int i = 0; i < 4; i++) {
        int b = ty * 4 + i;
        float4 v;
        if (b < cnt) {
            v.x = acc[i][0] + fcb[n + 0];
            v.y = acc[i][1] + fcb[n + 1];
            v.z = acc[i][2] + fcb[n + 2];
            v.w = acc[i][3] + fcb[n + 3];
        } else {
            v = make_float4(0.f, 0.f, 0.f, 0.f);
        }
        *(float4*)&out[((long long)b * TDEC + s) * VOCAB + n] = v;
    }
}

// ---------------- launch ----------------
extern "C" void kernel_launch(void* const* d_in, const int* in_sizes, int n_in,
                              void* d_out, int out_size)
{
    const float* enc  = (const float*)d_in[0];
    const void*  caps = d_in[1];
    const void*  clen = d_in[2];
    const float* emb  = (const float*)d_in[3];
    const float* Wih  = (const float*)d_in[4];
    const float* Whh  = (const float*)d_in[5];
    const float* bih  = (const float*)d_in[6];
    const float* bhh  = (const float*)d_in[7];
    const float* fcW  = (const float*)d_in[8];
    const float* fcb  = (const float*)d_in[9];
    float* out = (float*)d_out;

    k_setup<<<1, 64>>>(clen, out, out_size);
    k_gather<<<TCAP * BATCH, 256>>>(enc, caps, emb);
    k_gemm_inputs<<<dim3(32, 64), 256>>>(Wih, bih, bhh);
    k_step0<<<(BATCH * DDIM) / 256, 256>>>();
    for (int s = 1; s <= TDEC; s++)
        k_step<<<128, 256>>>(s, Whh);
    k_fc<<<dim3(TDEC, VOCAB / 64), 256>>>(fcW, fcb, out);
}

// round 4
// speedup vs baseline: 2.0624x; 2.0624x over previous
#include <cuda_runtime.h>
#include <cuda_bf16.h>
#include <cstdint>

#define BATCH 64
#define TCAP  32
#define VOCAB 32000
#define EDIM  1024
#define DDIM  1024
#define TDEC  31
#define NG    4096   // 4*DDIM
#define MROWS 2048

// ---------------- static scratch ----------------
__device__ int   d_sortind[BATCH];
__device__ int   d_declen[BATCH];
__device__ int   d_cnt[TDEC];
__device__ int   d_rowstart[TDEC];
__device__ int   d_Mact;
__device__ int   d_M2048 = 2048;
__device__ int   d_i64;
__device__ long long d_rowout[MROWS];
__device__ __align__(16) float d_gatesx[TCAP * BATCH * NG];   // 32 MB
__device__ __align__(16) float d_hbuf[2][BATCH * DDIM];
__device__ __align__(16) float d_c[BATCH * DDIM];
__device__ __align__(16) __nv_bfloat16 d_Xhi[MROWS * EDIM];
__device__ __align__(16) __nv_bfloat16 d_Xlo[MROWS * EDIM];
__device__ __align__(16) __nv_bfloat16 d_Hchi[MROWS * DDIM];  // compacted h rows
__device__ __align__(16) __nv_bfloat16 d_Hclo[MROWS * DDIM];
__device__ __align__(16) __nv_bfloat16 d_WihHi[NG * EDIM];
__device__ __align__(16) __nv_bfloat16 d_WihLo[NG * EDIM];
__device__ __align__(16) __nv_bfloat16 d_WfcHi[VOCAB * DDIM];
__device__ __align__(16) __nv_bfloat16 d_WfcLo[VOCAB * DDIM];

__device__ __forceinline__ float sigmf(float x) { return 1.0f / (1.0f + expf(-x)); }

__device__ __forceinline__ uint32_t smem_u32(const void* p) {
    uint32_t a;
    asm("{ .reg .u64 t; cvta.to.shared.u64 t, %1; cvt.u32.u64 %0, t; }" : "=r"(a) : "l"(p));
    return a;
}

#define LDSM4(r0, r1, r2, r3, a) \
    asm volatile("ldmatrix.sync.aligned.m8n8.x4.shared.b16 {%0,%1,%2,%3}, [%4];" \
                 : "=r"(r0), "=r"(r1), "=r"(r2), "=r"(r3) : "r"(a))
#define LDSM2(r0, r1, a) \
    asm volatile("ldmatrix.sync.aligned.m8n8.x2.shared.b16 {%0,%1}, [%2];" \
                 : "=r"(r0), "=r"(r1) : "r"(a))
#define MMA16816(c, a, b) \
    asm volatile("mma.sync.aligned.m16n8k16.row.col.f32.bf16.bf16.f32 " \
                 "{%0,%1,%2,%3}, {%4,%5,%6,%7}, {%8,%9}, {%0,%1,%2,%3};" \
                 : "+f"((c)[0]), "+f"((c)[1]), "+f"((c)[2]), "+f"((c)[3]) \
                 : "r"((a)[0]), "r"((a)[1]), "r"((a)[2]), "r"((a)[3]), "r"((b)[0]), "r"((b)[1]))
#define CPASYNC16(dst, src) \
    asm volatile("cp.async.cg.shared.global [%0], [%1], 16;" :: "r"(dst), "l"(src))

// ---------------- setup ----------------
__global__ void k_setup(const void* __restrict__ cap_len_raw,
                        float* __restrict__ out, int out_size)
{
    __shared__ int len[BATCH];
    const int* p32 = (const int*)cap_len_raw;
    int is64 = (p32[1] == 0) ? 1 : 0;   // lengths in [2,32]; int64 high word == 0
    int i = threadIdx.x;
    if (i == 0) d_i64 = is64;
    if (i < BATCH) len[i] = p32[i << is64];
    __syncthreads();
    if (i < BATCH) {
        int li = len[i], r = 0;
        for (int j = 0; j < BATCH; j++) {
            int lj = len[j];
            if (lj > li || (lj == li && j < i)) r++;
        }
        d_sortind[r] = i;
        d_declen[r]  = li - 1;
    }
    __syncthreads();
    if (i < TDEC) {
        int c = 0;
        for (int b = 0; b < BATCH; b++)
            if (d_declen[b] > i) c++;
        d_cnt[i] = c;
    }
    __syncthreads();
    if (i == 0) {
        int acc = 0;
        for (int s = 0; s < TDEC; s++) { d_rowstart[s] = acc; acc += d_cnt[s]; }
        d_Mact = acc;
    }
    __syncthreads();
    for (int s = 0; s < TDEC; s++)
        if (i < d_cnt[s])
            d_rowout[d_rowstart[s] + i] = ((long long)i * TDEC + s) * VOCAB;
    long long base = (long long)BATCH * TDEC * VOCAB;
    if (out_size >= (int)(base + 2 * BATCH) && i < BATCH) {
        out[base + i]         = (float)d_declen[i];
        out[base + BATCH + i] = (float)d_sortind[i];
    }
}

// ---------------- gather: X as bf16 hi/lo ----------------
__global__ void __launch_bounds__(256) k_gather(const float* __restrict__ enc,
                                                const void* __restrict__ caps_raw,
                                                const float* __restrict__ emb)
{
    int row = blockIdx.x;          // t*BATCH + b
    int t = row >> 6, b = row & 63;
    int sb = d_sortind[b];
    const float* src;
    if (t == 0) {
        src = enc + (long long)sb * EDIM;
    } else {
        int idx = sb * TCAP + (t - 1);
        int tok = ((const int*)caps_raw)[idx << d_i64];
        src = emb + (long long)tok * EDIM;
    }
    float4 v = ((const float4*)src)[threadIdx.x];
    __nv_bfloat16 hx = __float2bfloat16(v.x), hy = __float2bfloat16(v.y);
    __nv_bfloat16 hz = __float2bfloat16(v.z), hw = __float2bfloat16(v.w);
    __nv_bfloat162 hA; hA.x = hx; hA.y = hy;
    __nv_bfloat162 hB; hB.x = hz; hB.y = hw;
    __nv_bfloat162 lA, lB;
    lA.x = __float2bfloat16(v.x - __bfloat162float(hx));
    lA.y = __float2bfloat16(v.y - __bfloat162float(hy));
    lB.x = __float2bfloat16(v.z - __bfloat162float(hz));
    lB.y = __float2bfloat16(v.w - __bfloat162float(hw));
    size_t o2 = (size_t)row * (EDIM / 2) + threadIdx.x * 2;
    ((__nv_bfloat162*)d_Xhi)[o2]     = hA;
    ((__nv_bfloat162*)d_Xhi)[o2 + 1] = hB;
    ((__nv_bfloat162*)d_Xlo)[o2]     = lA;
    ((__nv_bfloat162*)d_Xlo)[o2 + 1] = lB;
}

// ---------------- split weights f32 -> bf16 hi/lo ----------------
__global__ void __launch_bounds__(256) k_split(const float4* __restrict__ src,
                                               __nv_bfloat16* __restrict__ hi,
                                               __nv_bfloat16* __restrict__ lo, int n4)
{
    int i = blockIdx.x * 256 + threadIdx.x;
    if (i >= n4) return;
    float4 v = src[i];
    __nv_bfloat16 hx = __float2bfloat16(v.x), hy = __float2bfloat16(v.y);
    __nv_bfloat16 hz = __float2bfloat16(v.z), hw = __float2bfloat16(v.w);
    __nv_bfloat162 hA; hA.x = hx; hA.y = hy;
    __nv_bfloat162 hB; hB.x = hz; hB.y = hw;
    __nv_bfloat162 lA, lB;
    lA.x = __float2bfloat16(v.x - __bfloat162float(hx));
    lA.y = __float2bfloat16(v.y - __bfloat162float(hy));
    lB.x = __float2bfloat16(v.z - __bfloat162float(hz));
    lB.y = __float2bfloat16(v.w - __bfloat162float(hw));
    ((__nv_bfloat162*)hi)[2 * i]     = hA;
    ((__nv_bfloat162*)hi)[2 * i + 1] = hB;
    ((__nv_bfloat162*)lo)[2 * i]     = lA;
    ((__nv_bfloat162*)lo)[2 * i + 1] = lB;
}

// ================= mma.sync GEMM =================
// C[M,N] = Ahi@Bhi^T + Alo@Bhi^T + Ahi@Blo^T   (bf16 inputs, fp32 accum, K=1024)
// Block 128x128, BK=32, 8 warps (warp tile 64x32), cp.async double buffer.
// Smem rows padded to 80B for conflict-free ldmatrix.
// mode 0: out rows m0+row, stride NG, bias1+bias2
// mode 1: out scattered via rowout[m], bias1; rows >= *pMact skipped
#define OPB   10240            // bytes per operand tile (128 rows x 80B)
#define BUFB  (4 * OPB)        // 40960 per buffer
#define SMEMB (2 * BUFB)       // 81920

__global__ void __launch_bounds__(256, 1) k_mma(
    const __nv_bfloat16* __restrict__ Ahi, const __nv_bfloat16* __restrict__ Alo,
    const __nv_bfloat16* __restrict__ Bhi, const __nv_bfloat16* __restrict__ Blo,
    const float* __restrict__ bias1, const float* __restrict__ bias2,
    float* __restrict__ outp, const long long* __restrict__ rowout,
    const int* __restrict__ pMact, int mode)
{
    extern __shared__ char smem[];
    int tid = threadIdx.x;
    int m0 = blockIdx.x * 128;
    int n0 = blockIdx.y * 128;
    int Mact = *pMact;
    if (m0 >= Mact) return;

    uint32_t sb = smem_u32(smem);
    int wid = tid >> 5, lane = tid & 31;
    int wm = wid & 1, wn = wid >> 1;

    const char* gA[2] = { (const char*)Ahi, (const char*)Alo };
    const char* gB[2] = { (const char*)Bhi, (const char*)Blo };

    // ---- async load of one K-chunk (32) into buffer ----
    auto load_chunk = [&](int c, int buf) {
        uint32_t base = sb + buf * BUFB;
#pragma unroll
        for (int i = 0; i < 8; i++) {
            int gid = tid + i * 256;
            int op = gid >> 9;            // 0 Ahi, 1 Alo, 2 Bhi, 3 Blo
            int idx = gid & 511;
            int row = idx >> 2, cc = idx & 3;
            const char* src;
            if (op < 2) src = gA[op]     + ((size_t)(m0 + row) << 11) + c * 64 + cc * 16;
            else        src = gB[op - 2] + ((size_t)(n0 + row) << 11) + c * 64 + cc * 16;
            uint32_t dst = base + op * OPB + row * 80 + cc * 16;
            CPASYNC16(dst, src);
        }
        asm volatile("cp.async.commit_group;");
    };

    float acc[4][4][4];
#pragma unroll
    for (int a = 0; a < 4; a++)
#pragma unroll
        for (int b = 0; b < 4; b++)
#pragma unroll
            for (int q = 0; q < 4; q++) acc[a][b][q] = 0.f;

    load_chunk(0, 0);

    for (int c = 0; c < 32; c++) {
        int buf = c & 1;
        if (c < 31) load_chunk(c + 1, buf ^ 1);
        if (c < 31) asm volatile("cp.async.wait_group 1;");
        else        asm volatile("cp.async.wait_group 0;");
        __syncthreads();

        uint32_t sbuf = sb + buf * BUFB;
#pragma unroll
        for (int kk = 0; kk < 2; kk++) {
            uint32_t ah[4][4], al[4][4], bh[4][2], bl[4][2];
            uint32_t abase = sbuf + (wm * 64 + (lane & 15)) * 80 + (lane >> 4) * 16 + kk * 32;
#pragma unroll
            for (int mi = 0; mi < 4; mi++)
                LDSM4(ah[mi][0], ah[mi][1], ah[mi][2], ah[mi][3], abase + mi * 1280);
#pragma unroll
            for (int mi = 0; mi < 4; mi++)
                LDSM4(al[mi][0], al[mi][1], al[mi][2], al[mi][3], abase + OPB + mi * 1280);
            uint32_t bbase = sbuf + 2 * OPB + (wn * 32 + (lane & 7)) * 80 + ((lane >> 3) & 1) * 16 + kk * 32;
#pragma unroll
            for (int ni = 0; ni < 4; ni++)
                LDSM2(bh[ni][0], bh[ni][1], bbase + ni * 640);
#pragma unroll
            for (int ni = 0; ni < 4; ni++)
                LDSM2(bl[ni][0], bl[ni][1], bbase + OPB + ni * 640);
#pragma unroll
            for (int mi = 0; mi < 4; mi++)
#pragma unroll
                for (int ni = 0; ni < 4; ni++) {
                    MMA16816(acc[mi][ni], ah[mi], bh[ni]);
                    MMA16816(acc[mi][ni], al[mi], bh[ni]);
                    MMA16816(acc[mi][ni], ah[mi], bl[ni]);
                }
        }
        __syncthreads();
    }

    // ---- stage C through smem for coalesced writeout ----
    float* Cst = (float*)smem;           // 128 x 132
#pragma unroll
    for (int mi = 0; mi < 4; mi++)
#pragma unroll
        for (int ni = 0; ni < 4; ni++) {
            int r = wm * 64 + mi * 16 + (lane >> 2);
            int cbase = wn * 32 + ni * 8 + (lane & 3) * 2;
            Cst[r * 132 + cbase]           = acc[mi][ni][0];
            Cst[r * 132 + cbase + 1]       = acc[mi][ni][1];
            Cst[(r + 8) * 132 + cbase]     = acc[mi][ni][2];
            Cst[(r + 8) * 132 + cbase + 1] = acc[mi][ni][3];
        }
    __syncthreads();

    for (int it = tid; it < 128 * 32; it += 256) {
        int row = it >> 5;
        int col = (it & 31) * 4;
        int m = m0 + row;
        if (mode == 1 && m >= Mact) continue;
        float4 v = *(float4*)&Cst[row * 132 + col];
        float4 b1 = *(const float4*)(bias1 + n0 + col);
        v.x += b1.x; v.y += b1.y; v.z += b1.z; v.w += b1.w;
        float* dst;
        if (mode == 0) {
            float4 b2 = *(const float4*)(bias2 + n0 + col);
            v.x += b2.x; v.y += b2.y; v.z += b2.z; v.w += b2.w;
            dst = outp + (size_t)m * NG + n0 + col;
        } else {
            dst = outp + rowout[m] + n0 + col;
        }
        *(float4*)dst = v;
    }
}

// ---------------- step 0 ----------------
__global__ void __launch_bounds__(256) k_step0()
{
    int g = blockIdx.x * 256 + threadIdx.x;
    int b = g >> 10, d = g & 1023;
    const float* gx = d_gatesx + (long long)b * NG;
    float gi = gx[d];
    float gg = gx[2 * DDIM + d];
    float go = gx[3 * DDIM + d];
    float c = sigmf(gi) * tanhf(gg);
    float h = sigmf(go) * tanhf(c);
    d_c[g] = c;
    d_hbuf[0][g] = h;
}

// ---------------- recurrent step ----------------
__global__ void __launch_bounds__(256) k_step(int s, const float* __restrict__ Whh)
{
    __shared__ float Hs[16][64];
    __shared__ float Ws[16][32];
    __shared__ float Gs[64][32];

    int tid = threadIdx.x;
    int d0  = blockIdx.x * 8;
    int cnt = d_cnt[s - 1];
    int rs  = d_rowstart[s - 1];
    int rp  = (s - 1) & 1, wp = s & 1;
    const float* hin  = d_hbuf[rp];
    float*       hout = d_hbuf[wp];

    int tx = tid & 15, ty = tid >> 4;
    int lrH = tid >> 2, kqH = (tid & 3) * 4;
    bool skip = (ty * 4 >= cnt);

    float acc[4][2] = {};
    for (int k0 = 0; k0 < DDIM; k0 += 16) {
        float4 hv = *(const float4*)(hin + (long long)lrH * DDIM + k0 + kqH);
        Hs[kqH + 0][lrH] = hv.x; Hs[kqH + 1][lrH] = hv.y;
        Hs[kqH + 2][lrH] = hv.z; Hs[kqH + 3][lrH] = hv.w;
        if (tid < 128) {
            int r = tid >> 2, kq = (tid & 3) * 4;
            int wrow = (r >> 3) * DDIM + d0 + (r & 7);
            float4 wv = *(const float4*)(Whh + (long long)wrow * DDIM + k0 + kq);
            Ws[kq + 0][r] = wv.x; Ws[kq + 1][r] = wv.y;
            Ws[kq + 2][r] = wv.z; Ws[kq + 3][r] = wv.w;
        }
        __syncthreads();
        if (!skip) {
#pragma unroll
            for (int k = 0; k < 16; k++) {
                float4 av = *(const float4*)&Hs[k][ty * 4];
                float2 bw = *(const float2*)&Ws[k][tx * 2];
                float ar[4] = {av.x, av.y, av.z, av.w};
#pragma unroll
                for (int i = 0; i < 4; i++) {
                    acc[i][0] += ar[i] * bw.x;
                    acc[i][1] += ar[i] * bw.y;
                }
            }
        }
        __syncthreads();
    }

    if (!skip) {
#pragma unroll
        for (int i = 0; i < 4; i++)
#pragma unroll
            for (int j = 0; j < 2; j++) {
                int row = ty * 4 + i;
                int col = tx * 2 + j;
                int gate = col >> 3, jj = col & 7;
                Gs[row][col] = acc[i][j] +
                    d_gatesx[((long long)s * BATCH + row) * NG + gate * DDIM + d0 + jj];
            }
    }
    __syncthreads();

    for (int it = tid; it < BATCH * 8; it += 256) {
        int b = it >> 3, j = it & 7;
        int hidx = b * DDIM + d0 + j;
        float hval;
        if (b < cnt) {
            float gi = Gs[b][j],      gf = Gs[b][8 + j];
            float gg = Gs[b][16 + j], go = Gs[b][24 + j];
            float cold = d_c[hidx];
            float cn = sigmf(gf) * cold + sigmf(gi) * tanhf(gg);
            float hn = sigmf(go) * tanhf(cn);
            d_c[hidx] = cn;
            hval = hn;
            // write compacted bf16 hi/lo row for the fc GEMM
            __nv_bfloat16 hh = __float2bfloat16(hval);
            __nv_bfloat16 hl = __float2bfloat16(hval - __bfloat162float(hh));
            size_t o = (size_t)(rs + b) * DDIM + d0 + j;
            d_Hchi[o] = hh;
            d_Hclo[o] = hl;
        } else {
            hval = hin[hidx];
        }
        hout[hidx] = hval;
    }
}

// ---------------- launch ----------------
extern "C" void kernel_launch(void* const* d_in, const int* in_sizes, int n_in,
                              void* d_out, int out_size)
{
    const float* enc  = (const float*)d_in[0];
    const void*  caps = d_in[1];
    const void*  clen = d_in[2];
    const float* emb  = (const float*)d_in[3];
    const float* Wih  = (const float*)d_in[4];
    const float* Whh  = (const float*)d_in[5];
    const float* bih  = (const float*)d_in[6];
    const float* bhh  = (const float*)d_in[7];
    const float* fcW  = (const float*)d_in[8];
    const float* fcb  = (const float*)d_in[9];
    float* out = (float*)d_out;

    static int inited = 0;
    if (!inited) {
        cudaFuncSetAttribute(k_mma, cudaFuncAttributeMaxDynamicSharedMemorySize, SMEMB);
        inited = 1;
    }

    __nv_bfloat16 *pXhi, *pXlo, *pHchi, *pHclo, *pWihHi, *pWihLo, *pWfcHi, *pWfcLo;
    float* pGatesx;
    long long* pRowout;
    int *pMact, *pM2048;
    cudaGetSymbolAddress((void**)&pXhi, d_Xhi);
    cudaGetSymbolAddress((void**)&pXlo, d_Xlo);
    cudaGetSymbolAddress((void**)&pHchi, d_Hchi);
    cudaGetSymbolAddress((void**)&pHclo, d_Hclo);
    cudaGetSymbolAddress((void**)&pWihHi, d_WihHi);
    cudaGetSymbolAddress((void**)&pWihLo, d_WihLo);
    cudaGetSymbolAddress((void**)&pWfcHi, d_WfcHi);
    cudaGetSymbolAddress((void**)&pWfcLo, d_WfcLo);
    cudaGetSymbolAddress((void**)&pGatesx, d_gatesx);
    cudaGetSymbolAddress((void**)&pRowout, d_rowout);
    cudaGetSymbolAddress((void**)&pMact, d_Mact);
    cudaGetSymbolAddress((void**)&pM2048, d_M2048);

    // zero the full output (masked rows) and the compacted-H pads
    cudaMemsetAsync(out, 0, (size_t)out_size * sizeof(float));
    cudaMemsetAsync(pHchi, 0, (size_t)MROWS * DDIM * sizeof(__nv_bfloat16));
    cudaMemsetAsync(pHclo, 0, (size_t)MROWS * DDIM * sizeof(__nv_bfloat16));

    k_setup<<<1, 64>>>(clen, out, out_size);
    k_gather<<<TCAP * BATCH, 256>>>(enc, caps, emb);
    k_split<<<(NG * EDIM / 4 + 255) / 256, 256>>>((const float4*)Wih, pWihHi, pWihLo, NG * EDIM / 4);
    k_split<<<(VOCAB * DDIM / 4 + 255) / 256, 256>>>((const float4*)fcW, pWfcHi, pWfcLo, VOCAB * DDIM / 4);

    // gates_x = X @ Wih^T + bih + bhh   (M=2048, N=4096)
    k_mma<<<dim3(16, 32), 256, SMEMB>>>(pXhi, pXlo, pWihHi, pWihLo,
                                        bih, bhh, pGatesx, nullptr, pM2048, 0);

    k_step0<<<(BATCH * DDIM) / 256, 256>>>();
    for (int s = 1; s <= TDEC; s++)
        k_step<<<128, 256>>>(s, Whh);

    // predictions = Hc @ fcW^T + fcb, scattered  (M=Mact compacted, N=32000)
    k_mma<<<dim3(16, 250), 256, SMEMB>>>(pHchi, pHclo, pWfcHi, pWfcLo,
                                         fcb, nullptr, out, pRowout, pMact, 1);
}

// round 5
// speedup vs baseline: 2.1419x; 1.0385x over previous
#include <cuda_runtime.h>
#include <cuda_bf16.h>
#include <cstdint>

#define BATCH 64
#define TCAP  32
#define VOCAB 32000
#define EDIM  1024
#define DDIM  1024
#define TDEC  31
#define NG    4096   // 4*DDIM
#define MROWS 2048

// ---------------- static scratch ----------------
__device__ int   d_sortind[BATCH];
__device__ int   d_declen[BATCH];
__device__ int   d_cnt[TDEC];
__device__ int   d_rowstart[TDEC];
__device__ int   d_Mact;
__device__ int   d_M2048 = 2048;
__device__ int   d_i64;
__device__ long long d_rowout[MROWS];
__device__ __align__(16) float d_gatesx[TCAP * BATCH * NG];   // 32 MB
__device__ __align__(16) float d_hbuf[2][BATCH * DDIM];
__device__ __align__(16) float d_c[BATCH * DDIM];
__device__ __align__(16) __nv_bfloat16 d_Xhi[MROWS * EDIM];
__device__ __align__(16) __nv_bfloat16 d_Xlo[MROWS * EDIM];
__device__ __align__(16) __nv_bfloat16 d_Hchi[MROWS * DDIM];  // compacted h rows
__device__ __align__(16) __nv_bfloat16 d_Hclo[MROWS * DDIM];
__device__ __align__(16) __nv_bfloat16 d_WihHi[NG * EDIM];
__device__ __align__(16) __nv_bfloat16 d_WihLo[NG * EDIM];
__device__ __align__(16) __nv_bfloat16 d_WfcHi[VOCAB * DDIM];
__device__ __align__(16) __nv_bfloat16 d_WfcLo[VOCAB * DDIM];

__device__ __forceinline__ float sigmf(float x) { return 1.0f / (1.0f + expf(-x)); }

__device__ __forceinline__ uint32_t smem_u32(const void* p) {
    uint32_t a;
    asm("{ .reg .u64 t; cvta.to.shared.u64 t, %1; cvt.u32.u64 %0, t; }" : "=r"(a) : "l"(p));
    return a;
}

#define LDSM4(r0, r1, r2, r3, a) \
    asm volatile("ldmatrix.sync.aligned.m8n8.x4.shared.b16 {%0,%1,%2,%3}, [%4];" \
                 : "=r"(r0), "=r"(r1), "=r"(r2), "=r"(r3) : "r"(a))
#define LDSM2(r0, r1, a) \
    asm volatile("ldmatrix.sync.aligned.m8n8.x2.shared.b16 {%0,%1}, [%2];" \
                 : "=r"(r0), "=r"(r1) : "r"(a))
#define MMA16816(c, a, b) \
    asm volatile("mma.sync.aligned.m16n8k16.row.col.f32.bf16.bf16.f32 " \
                 "{%0,%1,%2,%3}, {%4,%5,%6,%7}, {%8,%9}, {%0,%1,%2,%3};" \
                 : "+f"((c)[0]), "+f"((c)[1]), "+f"((c)[2]), "+f"((c)[3]) \
                 : "r"((a)[0]), "r"((a)[1]), "r"((a)[2]), "r"((a)[3]), "r"((b)[0]), "r"((b)[1]))
#define CPASYNC16(dst, src) \
    asm volatile("cp.async.cg.shared.global [%0], [%1], 16;" :: "r"(dst), "l"(src))

// ---------------- setup ----------------
__global__ void k_setup(const void* __restrict__ cap_len_raw,
                        float* __restrict__ out, int out_size)
{
    __shared__ int len[BATCH];
    const int* p32 = (const int*)cap_len_raw;
    int is64 = (p32[1] == 0) ? 1 : 0;   // lengths in [2,32]; int64 high word == 0
    int i = threadIdx.x;
    if (i == 0) d_i64 = is64;
    if (i < BATCH) len[i] = p32[i << is64];
    __syncthreads();
    if (i < BATCH) {
        int li = len[i], r = 0;
        for (int j = 0; j < BATCH; j++) {
            int lj = len[j];
            if (lj > li || (lj == li && j < i)) r++;
        }
        d_sortind[r] = i;
        d_declen[r]  = li - 1;
    }
    __syncthreads();
    if (i < TDEC) {
        int c = 0;
        for (int b = 0; b < BATCH; b++)
            if (d_declen[b] > i) c++;
        d_cnt[i] = c;
    }
    __syncthreads();
    if (i == 0) {
        int acc = 0;
        for (int s = 0; s < TDEC; s++) { d_rowstart[s] = acc; acc += d_cnt[s]; }
        d_Mact = acc;
    }
    __syncthreads();
    for (int s = 0; s < TDEC; s++)
        if (i < d_cnt[s])
            d_rowout[d_rowstart[s] + i] = ((long long)i * TDEC + s) * VOCAB;
    long long base = (long long)BATCH * TDEC * VOCAB;
    if (out_size >= (int)(base + 2 * BATCH) && i < BATCH) {
        out[base + i]         = (float)d_declen[i];
        out[base + BATCH + i] = (float)d_sortind[i];
    }
}

// ---------------- gather: X as bf16 hi/lo ----------------
__global__ void __launch_bounds__(256) k_gather(const float* __restrict__ enc,
                                                const void* __restrict__ caps_raw,
                                                const float* __restrict__ emb)
{
    int row = blockIdx.x;          // t*BATCH + b
    int t = row >> 6, b = row & 63;
    int sb = d_sortind[b];
    const float* src;
    if (t == 0) {
        src = enc + (long long)sb * EDIM;
    } else {
        int idx = sb * TCAP + (t - 1);
        int tok = ((const int*)caps_raw)[idx << d_i64];
        src = emb + (long long)tok * EDIM;
    }
    float4 v = ((const float4*)src)[threadIdx.x];
    __nv_bfloat16 hx = __float2bfloat16(v.x), hy = __float2bfloat16(v.y);
    __nv_bfloat16 hz = __float2bfloat16(v.z), hw = __float2bfloat16(v.w);
    __nv_bfloat162 hA; hA.x = hx; hA.y = hy;
    __nv_bfloat162 hB; hB.x = hz; hB.y = hw;
    __nv_bfloat162 lA, lB;
    lA.x = __float2bfloat16(v.x - __bfloat162float(hx));
    lA.y = __float2bfloat16(v.y - __bfloat162float(hy));
    lB.x = __float2bfloat16(v.z - __bfloat162float(hz));
    lB.y = __float2bfloat16(v.w - __bfloat162float(hw));
    size_t o2 = (size_t)row * (EDIM / 2) + threadIdx.x * 2;
    ((__nv_bfloat162*)d_Xhi)[o2]     = hA;
    ((__nv_bfloat162*)d_Xhi)[o2 + 1] = hB;
    ((__nv_bfloat162*)d_Xlo)[o2]     = lA;
    ((__nv_bfloat162*)d_Xlo)[o2 + 1] = lB;
}

// ---------------- split weights f32 -> bf16 hi/lo ----------------
__global__ void __launch_bounds__(256) k_split(const float4* __restrict__ src,
                                               __nv_bfloat16* __restrict__ hi,
                                               __nv_bfloat16* __restrict__ lo, int n4)
{
    int i = blockIdx.x * 256 + threadIdx.x;
    if (i >= n4) return;
    float4 v = src[i];
    __nv_bfloat16 hx = __float2bfloat16(v.x), hy = __float2bfloat16(v.y);
    __nv_bfloat16 hz = __float2bfloat16(v.z), hw = __float2bfloat16(v.w);
    __nv_bfloat162 hA; hA.x = hx; hA.y = hy;
    __nv_bfloat162 hB; hB.x = hz; hB.y = hw;
    __nv_bfloat162 lA, lB;
    lA.x = __float2bfloat16(v.x - __bfloat162float(hx));
    lA.y = __float2bfloat16(v.y - __bfloat162float(hy));
    lB.x = __float2bfloat16(v.z - __bfloat162float(hz));
    lB.y = __float2bfloat16(v.w - __bfloat162float(hw));
    ((__nv_bfloat162*)hi)[2 * i]     = hA;
    ((__nv_bfloat162*)hi)[2 * i + 1] = hB;
    ((__nv_bfloat162*)lo)[2 * i]     = lA;
    ((__nv_bfloat162*)lo)[2 * i + 1] = lB;
}

// ================= mma.sync GEMM =================
// C[M,N] = Ahi@Bhi^T + Alo@Bhi^T + Ahi@Blo^T   (bf16, fp32 accum, K=1024)
// Block 128x128, BK=64, 3-stage cp.async pipeline, 8 warps (warp tile 64x32).
// Smem rows padded to 144B (64 bf16 + 16B) -> conflict-free ldmatrix.
// One __syncthreads per K-chunk.
#define OPB2   18432                 // 128 rows x 144B per operand
#define STGB   (4 * OPB2)            // 73728 per stage
#define NSTG   3
#define SMEMB  (NSTG * STGB)         // 221184
#define NCHUNK 16                    // 1024 / 64

__global__ void __launch_bounds__(256, 1) k_mma(
    const __nv_bfloat16* __restrict__ Ahi, const __nv_bfloat16* __restrict__ Alo,
    const __nv_bfloat16* __restrict__ Bhi, const __nv_bfloat16* __restrict__ Blo,
    const float* __restrict__ bias1, const float* __restrict__ bias2,
    float* __restrict__ outp, const long long* __restrict__ rowout,
    const int* __restrict__ pMact, int mode)
{
    extern __shared__ char smem[];
    int tid = threadIdx.x;
    int m0 = blockIdx.x * 128;
    int n0 = blockIdx.y * 128;
    int Mact = *pMact;
    if (m0 >= Mact) return;

    uint32_t sb = smem_u32(smem);
    int wid = tid >> 5, lane = tid & 31;
    int wm = wid & 1, wn = wid >> 1;

    const char* gA[2] = { (const char*)Ahi, (const char*)Alo };
    const char* gB[2] = { (const char*)Bhi, (const char*)Blo };

    // one K-chunk (64 cols = 128B/row) for 4 operands: 4096 x 16B, 16 per thread
    auto load_chunk = [&](int c, int slot) {
        uint32_t base = sb + slot * STGB;
#pragma unroll
        for (int i = 0; i < 16; i++) {
            int gid = tid + i * 256;
            int op  = gid >> 10;          // 0 Ahi, 1 Alo, 2 Bhi, 3 Blo
            int idx = gid & 1023;
            int row = idx >> 3, cc = idx & 7;
            const char* src;
            if (op < 2) src = gA[op]     + ((size_t)(m0 + row) << 11) + c * 128 + cc * 16;
            else        src = gB[op - 2] + ((size_t)(n0 + row) << 11) + c * 128 + cc * 16;
            CPASYNC16(base + op * OPB2 + row * 144 + cc * 16, src);
        }
        asm volatile("cp.async.commit_group;");
    };

    float acc[4][4][4];
#pragma unroll
    for (int a = 0; a < 4; a++)
#pragma unroll
        for (int b = 0; b < 4; b++)
#pragma unroll
            for (int q = 0; q < 4; q++) acc[a][b][q] = 0.f;

    load_chunk(0, 0);
    load_chunk(1, 1);

    for (int c = 0; c < NCHUNK; c++) {
        if (c < NCHUNK - 1) asm volatile("cp.async.wait_group 1;");
        else                asm volatile("cp.async.wait_group 0;");
        __syncthreads();
        if (c + 2 < NCHUNK) load_chunk(c + 2, (c + 2) % NSTG);

        uint32_t sbuf = sb + (c % NSTG) * STGB;
#pragma unroll
        for (int kk = 0; kk < 4; kk++) {
            uint32_t ah[4][4], al[4][4], bh[4][2], bl[4][2];
            uint32_t abase = sbuf + (wm * 64 + (lane & 15)) * 144 + (lane >> 4) * 16 + kk * 32;
#pragma unroll
            for (int mi = 0; mi < 4; mi++)
                LDSM4(ah[mi][0], ah[mi][1], ah[mi][2], ah[mi][3], abase + mi * 2304);
#pragma unroll
            for (int mi = 0; mi < 4; mi++)
                LDSM4(al[mi][0], al[mi][1], al[mi][2], al[mi][3], abase + OPB2 + mi * 2304);
            uint32_t bbase = sbuf + 2 * OPB2 + (wn * 32 + (lane & 7)) * 144 + ((lane >> 3) & 1) * 16 + kk * 32;
#pragma unroll
            for (int ni = 0; ni < 4; ni++)
                LDSM2(bh[ni][0], bh[ni][1], bbase + ni * 1152);
#pragma unroll
            for (int ni = 0; ni < 4; ni++)
                LDSM2(bl[ni][0], bl[ni][1], bbase + OPB2 + ni * 1152);
#pragma unroll
            for (int mi = 0; mi < 4; mi++)
#pragma unroll
                for (int ni = 0; ni < 4; ni++) {
                    MMA16816(acc[mi][ni], ah[mi], bh[ni]);
                    MMA16816(acc[mi][ni], al[mi], bh[ni]);
                    MMA16816(acc[mi][ni], ah[mi], bl[ni]);
                }
        }
    }
    __syncthreads();

    // ---- stage C through smem for coalesced writeout ----
    float* Cst = (float*)smem;           // 128 x 132
#pragma unroll
    for (int mi = 0; mi < 4; mi++)
#pragma unroll
        for (int ni = 0; ni < 4; ni++) {
            int r = wm * 64 + mi * 16 + (lane >> 2);
            int cbase = wn * 32 + ni * 8 + (lane & 3) * 2;
            Cst[r * 132 + cbase]           = acc[mi][ni][0];
            Cst[r * 132 + cbase + 1]       = acc[mi][ni][1];
            Cst[(r + 8) * 132 + cbase]     = acc[mi][ni][2];
            Cst[(r + 8) * 132 + cbase + 1] = acc[mi][ni][3];
        }
    __syncthreads();

    for (int it = tid; it < 128 * 32; it += 256) {
        int row = it >> 5;
        int col = (it & 31) * 4;
        int m = m0 + row;
        if (mode == 1 && m >= Mact) continue;
        float4 v = *(float4*)&Cst[row * 132 + col];
        float4 b1 = *(const float4*)(bias1 + n0 + col);
        v.x += b1.x; v.y += b1.y; v.z += b1.z; v.w += b1.w;
        float* dst;
        if (mode == 0) {
            float4 b2 = *(const float4*)(bias2 + n0 + col);
            v.x += b2.x; v.y += b2.y; v.z += b2.z; v.w += b2.w;
            dst = outp + (size_t)m * NG + n0 + col;
        } else {
            dst = outp + rowout[m] + n0 + col;
        }
        *(float4*)dst = v;
    }
}

// ---------------- step 0 ----------------
__global__ void __launch_bounds__(256) k_step0()
{
    int g = blockIdx.x * 256 + threadIdx.x;
    int b = g >> 10, d = g & 1023;
    const float* gx = d_gatesx + (long long)b * NG;
    float gi = gx[d];
    float gg = gx[2 * DDIM + d];
    float go = gx[3 * DDIM + d];
    float c = sigmf(gi) * tanhf(gg);
    float h = sigmf(go) * tanhf(c);
    d_c[g] = c;
    d_hbuf[0][g] = h;
}

// ---------------- recurrent step ----------------
__global__ void __launch_bounds__(256) k_step(int s, const float* __restrict__ Whh)
{
    __shared__ float Hs[16][64];
    __shared__ float Ws[16][32];
    __shared__ float Gs[64][32];

    int tid = threadIdx.x;
    int d0  = blockIdx.x * 8;
    int cnt = d_cnt[s - 1];
    int rs  = d_rowstart[s - 1];
    int rp  = (s - 1) & 1, wp = s & 1;
    const float* hin  = d_hbuf[rp];
    float*       hout = d_hbuf[wp];

    int tx = tid & 15, ty = tid >> 4;
    int lrH = tid >> 2, kqH = (tid & 3) * 4;
    bool skip = (ty * 4 >= cnt);

    float acc[4][2] = {};
    for (int k0 = 0; k0 < DDIM; k0 += 16) {
        float4 hv = *(const float4*)(hin + (long long)lrH * DDIM + k0 + kqH);
        Hs[kqH + 0][lrH] = hv.x; Hs[kqH + 1][lrH] = hv.y;
        Hs[kqH + 2][lrH] = hv.z; Hs[kqH + 3][lrH] = hv.w;
        if (tid < 128) {
            int r = tid >> 2, kq = (tid & 3) * 4;
            int wrow = (r >> 3) * DDIM + d0 + (r & 7);
            float4 wv = *(const float4*)(Whh + (long long)wrow * DDIM + k0 + kq);
            Ws[kq + 0][r] = wv.x; Ws[kq + 1][r] = wv.y;
            Ws[kq + 2][r] = wv.z; Ws[kq + 3][r] = wv.w;
        }
        __syncthreads();
        if (!skip) {
#pragma unroll
            for (int k = 0; k < 16; k++) {
                float4 av = *(const float4*)&Hs[k][ty * 4];
                float2 bw = *(const float2*)&Ws[k][tx * 2];
                float ar[4] = {av.x, av.y, av.z, av.w};
#pragma unroll
                for (int i = 0; i < 4; i++) {
                    acc[i][0] += ar[i] * bw.x;
                    acc[i][1] += ar[i] * bw.y;
                }
            }
        }
        __syncthreads();
    }

    if (!skip) {
#pragma unroll
        for (int i = 0; i < 4; i++)
#pragma unroll
            for (int j = 0; j < 2; j++) {
                int row = ty * 4 + i;
                int col = tx * 2 + j;
                int gate = col >> 3, jj = col & 7;
                Gs[row][col] = acc[i][j] +
                    d_gatesx[((long long)s * BATCH + row) * NG + gate * DDIM + d0 + jj];
            }
    }
    __syncthreads();

    for (int it = tid; it < BATCH * 8; it += 256) {
        int b = it >> 3, j = it & 7;
        int hidx = b * DDIM + d0 + j;
        float hval;
        if (b < cnt) {
            float gi = Gs[b][j],      gf = Gs[b][8 + j];
            float gg = Gs[b][16 + j], go = Gs[b][24 + j];
            float cold = d_c[hidx];
            float cn = sigmf(gf) * cold + sigmf(gi) * tanhf(gg);
            float hn = sigmf(go) * tanhf(cn);
            d_c[hidx] = cn;
            hval = hn;
            __nv_bfloat16 hh = __float2bfloat16(hval);
            __nv_bfloat16 hl = __float2bfloat16(hval - __bfloat162float(hh));
            size_t o = (size_t)(rs + b) * DDIM + d0 + j;
            d_Hchi[o] = hh;
            d_Hclo[o] = hl;
        } else {
            hval = hin[hidx];
        }
        hout[hidx] = hval;
    }
}

// ---------------- launch ----------------
extern "C" void kernel_launch(void* const* d_in, const int* in_sizes, int n_in,
                              void* d_out, int out_size)
{
    const float* enc  = (const float*)d_in[0];
    const void*  caps = d_in[1];
    const void*  clen = d_in[2];
    const float* emb  = (const float*)d_in[3];
    const float* Wih  = (const float*)d_in[4];
    const float* Whh  = (const float*)d_in[5];
    const float* bih  = (const float*)d_in[6];
    const float* bhh  = (const float*)d_in[7];
    const float* fcW  = (const float*)d_in[8];
    const float* fcb  = (const float*)d_in[9];
    float* out = (float*)d_out;

    static int inited = 0;
    if (!inited) {
        cudaFuncSetAttribute(k_mma, cudaFuncAttributeMaxDynamicSharedMemorySize, SMEMB);
        inited = 1;
    }

    __nv_bfloat16 *pXhi, *pXlo, *pHchi, *pHclo, *pWihHi, *pWihLo, *pWfcHi, *pWfcLo;
    float* pGatesx;
    long long* pRowout;
    int *pMact, *pM2048;
    cudaGetSymbolAddress((void**)&pXhi, d_Xhi);
    cudaGetSymbolAddress((void**)&pXlo, d_Xlo);
    cudaGetSymbolAddress((void**)&pHchi, d_Hchi);
    cudaGetSymbolAddress((void**)&pHclo, d_Hclo);
    cudaGetSymbolAddress((void**)&pWihHi, d_WihHi);
    cudaGetSymbolAddress((void**)&pWihLo, d_WihLo);
    cudaGetSymbolAddress((void**)&pWfcHi, d_WfcHi);
    cudaGetSymbolAddress((void**)&pWfcLo, d_WfcLo);
    cudaGetSymbolAddress((void**)&pGatesx, d_gatesx);
    cudaGetSymbolAddress((void**)&pRowout, d_rowout);
    cudaGetSymbolAddress((void**)&pMact, d_Mact);
    cudaGetSymbolAddress((void**)&pM2048, d_M2048);

    // zero the full output (masked rows) and the compacted-H pads
    cudaMemsetAsync(out, 0, (size_t)out_size * sizeof(float));
    cudaMemsetAsync(pHchi, 0, (size_t)MROWS * DDIM * sizeof(__nv_bfloat16));
    cudaMemsetAsync(pHclo, 0, (size_t)MROWS * DDIM * sizeof(__nv_bfloat16));

    k_setup<<<1, 64>>>(clen, out, out_size);
    k_gather<<<TCAP * BATCH, 256>>>(enc, caps, emb);
    k_split<<<(NG * EDIM / 4 + 255) / 256, 256>>>((const float4*)Wih, pWihHi, pWihLo, NG * EDIM / 4);
    k_split<<<(VOCAB * DDIM / 4 + 255) / 256, 256>>>((const float4*)fcW, pWfcHi, pWfcLo, VOCAB * DDIM / 4);

    // gates_x = X @ Wih^T + bih + bhh   (M=2048, N=4096)
    k_mma<<<dim3(16, 32), 256, SMEMB>>>(pXhi, pXlo, pWihHi, pWihLo,
                                        bih, bhh, pGatesx, nullptr, pM2048, 0);

    k_step0<<<(BATCH * DDIM) / 256, 256>>>();
    for (int s = 1; s <= TDEC; s++)
        k_step<<<128, 256>>>(s, Whh);

    // predictions = Hc @ fcW^T + fcb, scattered  (M=Mact compacted, N=32000)
    k_mma<<<dim3(16, 250), 256, SMEMB>>>(pHchi, pHclo, pWfcHi, pWfcLo,
                                         fcb, nullptr, out, pRowout, pMact, 1);
}

// round 7
// speedup vs baseline: 3.0887x; 1.4421x over previous
#include <cuda_runtime.h>
#include <cuda_bf16.h>
#include <cstdint>

#define BATCH 64
#define TCAP  32
#define VOCAB 32000
#define EDIM  1024
#define DDIM  1024
#define TDEC  31
#define NG    4096   // 4*DDIM
#define MROWS 2048
#define CROW  144    // padded bytes per row (64 bf16 = 128B + 16B pad)
#define NCHUNK 16    // K=1024 / 64

// ---------------- static scratch ----------------
__device__ int   d_sortind[BATCH];
__device__ int   d_declen[BATCH];
__device__ int   d_cnt[TDEC];
__device__ int   d_rowstart[TDEC];
__device__ int   d_Mact;
__device__ int   d_M2048 = 2048;
__device__ int   d_i64;
__device__ long long d_rowout[MROWS];
__device__ __align__(16) float d_gatesx[TCAP * BATCH * NG];   // 32 MB
__device__ __align__(16) float d_hbuf[2][BATCH * DDIM];
__device__ __align__(16) float d_c[BATCH * DDIM];
// chunked + padded bf16 operands: [chunk][row][144B]
__device__ __align__(16) char d_XhiC [NCHUNK * MROWS * CROW];   // 4.7 MB
__device__ __align__(16) char d_XloC [NCHUNK * MROWS * CROW];
__device__ __align__(16) char d_HchiC[NCHUNK * MROWS * CROW];
__device__ __align__(16) char d_HcloC[NCHUNK * MROWS * CROW];
__device__ __align__(16) char d_WihHiC[NCHUNK * NG * CROW];     // 9.4 MB
__device__ __align__(16) char d_WihLoC[NCHUNK * NG * CROW];
__device__ __align__(16) char d_WfcHiC[NCHUNK * VOCAB * CROW];  // 73.7 MB
__device__ __align__(16) char d_WfcLoC[NCHUNK * VOCAB * CROW];

__device__ __forceinline__ float sigmf(float x) { return 1.0f / (1.0f + expf(-x)); }

__device__ __forceinline__ uint32_t smem_u32(const void* p) {
    uint32_t a;
    asm("{ .reg .u64 t; cvta.to.shared.u64 t, %1; cvt.u32.u64 %0, t; }" : "=r"(a) : "l"(p));
    return a;
}

#define LDSM4(r0, r1, r2, r3, a) \
    asm volatile("ldmatrix.sync.aligned.m8n8.x4.shared.b16 {%0,%1,%2,%3}, [%4];" \
                 : "=r"(r0), "=r"(r1), "=r"(r2), "=r"(r3) : "r"(a))
#define LDSM2(r0, r1, a) \
    asm volatile("ldmatrix.sync.aligned.m8n8.x2.shared.b16 {%0,%1}, [%2];" \
                 : "=r"(r0), "=r"(r1) : "r"(a))
#define MMA16816(c, a, b) \
    asm volatile("mma.sync.aligned.m16n8k16.row.col.f32.bf16.bf16.f32 " \
                 "{%0,%1,%2,%3}, {%4,%5,%6,%7}, {%8,%9}, {%0,%1,%2,%3};" \
                 : "+f"((c)[0]), "+f"((c)[1]), "+f"((c)[2]), "+f"((c)[3]) \
                 : "r"((a)[0]), "r"((a)[1]), "r"((a)[2]), "r"((a)[3]), "r"((b)[0]), "r"((b)[1]))
#define MBAR_INIT(a, c)  asm volatile("mbarrier.init.shared.b64 [%0], %1;" :: "r"(a), "r"(c) : "memory")
#define MBAR_EXPECT(a, tx) asm volatile("mbarrier.arrive.expect_tx.shared.b64 _, [%0], %1;" :: "r"(a), "r"(tx) : "memory")
#define FENCE_ASYNC()    asm volatile("fence.proxy.async.shared::cta;" ::: "memory")
#define BULKCP(dst, src, sz, mb) \
    asm volatile("cp.async.bulk.shared::cluster.global.mbarrier::complete_tx::bytes [%0], [%1], %2, [%3];" \
                 :: "r"(dst), "l"(src), "r"(sz), "r"(mb) : "memory")

__device__ __forceinline__ void mbar_wait(uint32_t mb, uint32_t parity) {
    asm volatile(
        "{\n\t.reg .pred P;\n\t"
        "W%=:\n\t"
        "mbarrier.try_wait.parity.acquire.cta.shared::cta.b64 P, [%0], %1, 0x989680;\n\t"
        "@P bra.uni D%=;\n\t"
        "bra.uni W%=;\n\t"
        "D%=:\n\t}" :: "r"(mb), "r"(parity) : "memory");
}

// ---------------- setup ----------------
__global__ void k_setup(const void* __restrict__ cap_len_raw,
                        float* __restrict__ out, int out_size)
{
    __shared__ int len[BATCH];
    const int* p32 = (const int*)cap_len_raw;
    int is64 = (p32[1] == 0) ? 1 : 0;   // lengths in [2,32]; int64 high word == 0
    int i = threadIdx.x;
    if (i == 0) d_i64 = is64;
    if (i < BATCH) len[i] = p32[i << is64];
    __syncthreads();
    if (i < BATCH) {
        int li = len[i], r = 0;
        for (int j = 0; j < BATCH; j++) {
            int lj = len[j];
            if (lj > li || (lj == li && j < i)) r++;
        }
        d_sortind[r] = i;
        d_declen[r]  = li - 1;
    }
    __syncthreads();
    if (i < TDEC) {
        int c = 0;
        for (int b = 0; b < BATCH; b++)
            if (d_declen[b] > i) c++;
        d_cnt[i] = c;
    }
    __syncthreads();
    if (i == 0) {
        int acc = 0;
        for (int s = 0; s < TDEC; s++) { d_rowstart[s] = acc; acc += d_cnt[s]; }
        d_Mact = acc;
    }
    __syncthreads();
    for (int s = 0; s < TDEC; s++)
        if (i < d_cnt[s])
            d_rowout[d_rowstart[s] + i] = ((long long)i * TDEC + s) * VOCAB;
    long long base = (long long)BATCH * TDEC * VOCAB;
    if (out_size >= (int)(base + 2 * BATCH) && i < BATCH) {
        out[base + i]         = (float)d_declen[i];
        out[base + BATCH + i] = (float)d_sortind[i];
    }
}

// ---------------- gather: X as bf16 hi/lo into chunked layout ----------------
__global__ void __launch_bounds__(256) k_gather(const float* __restrict__ enc,
                                                const void* __restrict__ caps_raw,
                                                const float* __restrict__ emb)
{
    int row = blockIdx.x;          // t*BATCH + b
    int t = row >> 6, b = row & 63;
    int sb = d_sortind[b];
    const float* src;
    if (t == 0) {
        src = enc + (long long)sb * EDIM;
    } else {
        int idx = sb * TCAP + (t - 1);
        int tok = ((const int*)caps_raw)[idx << d_i64];
        src = emb + (long long)tok * EDIM;
    }
    float4 v = ((const float4*)src)[threadIdx.x];
    __nv_bfloat16 hx = __float2bfloat16(v.x), hy = __float2bfloat16(v.y);
    __nv_bfloat16 hz = __float2bfloat16(v.z), hw = __float2bfloat16(v.w);
    __nv_bfloat162 hA; hA.x = hx; hA.y = hy;
    __nv_bfloat162 hB; hB.x = hz; hB.y = hw;
    __nv_bfloat162 lA, lB;
    lA.x = __float2bfloat16(v.x - __bfloat162float(hx));
    lA.y = __float2bfloat16(v.y - __bfloat162float(hy));
    lB.x = __float2bfloat16(v.z - __bfloat162float(hz));
    lB.y = __float2bfloat16(v.w - __bfloat162float(hw));
    int col = threadIdx.x * 4;
    int ch = col >> 6, kc = col & 63;
    size_t off = ((size_t)ch * MROWS + row) * CROW + kc * 2;
    *(__nv_bfloat162*)(d_XhiC + off)     = hA;
    *(__nv_bfloat162*)(d_XhiC + off + 4) = hB;
    *(__nv_bfloat162*)(d_XloC + off)     = lA;
    *(__nv_bfloat162*)(d_XloC + off + 4) = lB;
}

// ---------------- split weights f32 -> bf16 hi/lo chunked ----------------
// grid.x = nrows, 256 threads: thread handles cols tid*4..tid*4+3 of row blockIdx.x
__global__ void __launch_bounds__(256) k_split(const float4* __restrict__ src,
                                               char* __restrict__ hiC,
                                               char* __restrict__ loC, int nrows)
{
    int r = blockIdx.x;
    int tid = threadIdx.x;
    float4 v = src[(size_t)r * 256 + tid];
    __nv_bfloat16 hx = __float2bfloat16(v.x), hy = __float2bfloat16(v.y);
    __nv_bfloat16 hz = __float2bfloat16(v.z), hw = __float2bfloat16(v.w);
    __nv_bfloat162 hA; hA.x = hx; hA.y = hy;
    __nv_bfloat162 hB; hB.x = hz; hB.y = hw;
    __nv_bfloat162 lA, lB;
    lA.x = __float2bfloat16(v.x - __bfloat162float(hx));
    lA.y = __float2bfloat16(v.y - __bfloat162float(hy));
    lB.x = __float2bfloat16(v.z - __bfloat162float(hz));
    lB.y = __float2bfloat16(v.w - __bfloat162float(hw));
    int col = tid * 4;
    int ch = col >> 6, kc = col & 63;
    size_t off = ((size_t)ch * nrows + r) * CROW + kc * 2;
    *(__nv_bfloat162*)(hiC + off)     = hA;
    *(__nv_bfloat162*)(hiC + off + 4) = hB;
    *(__nv_bfloat162*)(loC + off)     = lA;
    *(__nv_bfloat162*)(loC + off + 4) = lB;
}

// ================= bulk-copy mma.sync GEMM =================
// C[M,N] = Ahi@Bhi^T + Alo@Bhi^T + Ahi@Blo^T  (bf16, fp32 accum, K=1024)
// Operands in chunked gmem layout [chunk][row][144B]; one cp.async.bulk per
// operand tile per chunk (18KB contiguous). 3-stage mbarrier pipeline.
#define OPB2   (128 * CROW)          // 18432 per operand tile
#define STGB   (4 * OPB2)            // 73728 per stage
#define NSTG   3
#define SMEMB  (128 + NSTG * STGB)   // 221312

__global__ void __launch_bounds__(256, 1) k_mma(
    const char* __restrict__ AhiC, const char* __restrict__ AloC,
    const char* __restrict__ BhiC, const char* __restrict__ BloC,
    int arows, int brows,
    const float* __restrict__ bias1, const float* __restrict__ bias2,
    float* __restrict__ outp, const long long* __restrict__ rowout,
    const int* __restrict__ pMact, int mode)
{
    extern __shared__ char smem[];
    int tid = threadIdx.x;
    int m0 = blockIdx.x * 128;
    int n0 = blockIdx.y * 128;
    int Mact = *pMact;
    if (m0 >= Mact) return;

    uint32_t sb  = smem_u32(smem);
    uint32_t stg = sb + 128;
    int wid = tid >> 5, lane = tid & 31;
    int wm = wid & 1, wn = wid >> 1;

    if (tid == 0) { MBAR_INIT(sb + 0, 1); MBAR_INIT(sb + 8, 1); MBAR_INIT(sb + 16, 1); }
    FENCE_ASYNC();
    __syncthreads();

    const char* srcs[4] = { AhiC, AloC, BhiC, BloC };

    auto issue = [&](int c, int slot) {
        uint32_t mb = sb + slot * 8;
        MBAR_EXPECT(mb, 4 * OPB2);
#pragma unroll
        for (int op = 0; op < 4; op++) {
            int nr = (op < 2) ? arows : brows;
            int t0 = (op < 2) ? m0 : n0;
            const char* src = srcs[op] + ((size_t)c * nr + t0) * CROW;
            uint32_t dst = stg + slot * STGB + op * OPB2;
            BULKCP(dst, src, OPB2, mb);
        }
    };

    float acc[4][4][4];
#pragma unroll
    for (int a = 0; a < 4; a++)
#pragma unroll
        for (int b = 0; b < 4; b++)
#pragma unroll
            for (int q = 0; q < 4; q++) acc[a][b][q] = 0.f;

    if (tid == 0) { issue(0, 0); issue(1, 1); }
    int ph[3] = { 0, 0, 0 };

    for (int c = 0; c < NCHUNK; c++) {
        // stage (c+2)%3 was consumed at iteration c-1 (guarded by its __syncthreads)
        if (tid == 0 && c + 2 < NCHUNK) issue(c + 2, (c + 2) % 3);
        int st = c % 3;
        mbar_wait(sb + st * 8, ph[st]); ph[st] ^= 1;

        uint32_t sbuf = stg + st * STGB;
#pragma unroll
        for (int kk = 0; kk < 4; kk++) {
            uint32_t ah[4][4], al[4][4], bh[4][2], bl[4][2];
            uint32_t abase = sbuf + (wm * 64 + (lane & 15)) * CROW + (lane >> 4) * 16 + kk * 32;
#pragma unroll
            for (int mi = 0; mi < 4; mi++)
                LDSM4(ah[mi][0], ah[mi][1], ah[mi][2], ah[mi][3], abase + mi * 16 * CROW);
#pragma unroll
            for (int mi = 0; mi < 4; mi++)
                LDSM4(al[mi][0], al[mi][1], al[mi][2], al[mi][3], abase + OPB2 + mi * 16 * CROW);
            uint32_t bbase = sbuf + 2 * OPB2 + (wn * 32 + (lane & 7)) * CROW + ((lane >> 3) & 1) * 16 + kk * 32;
#pragma unroll
            for (int ni = 0; ni < 4; ni++)
                LDSM2(bh[ni][0], bh[ni][1], bbase + ni * 8 * CROW);
#pragma unroll
            for (int ni = 0; ni < 4; ni++)
                LDSM2(bl[ni][0], bl[ni][1], bbase + OPB2 + ni * 8 * CROW);
#pragma unroll
            for (int mi = 0; mi < 4; mi++)
#pragma unroll
                for (int ni = 0; ni < 4; ni++) {
                    MMA16816(acc[mi][ni], ah[mi], bh[ni]);
                    MMA16816(acc[mi][ni], al[mi], bh[ni]);
                    MMA16816(acc[mi][ni], ah[mi], bl[ni]);
                }
        }
        __syncthreads();   // stage free for reuse
    }

    // ---- stage C through smem for coalesced writeout ----
    float* Cst = (float*)smem;           // 128 x 132
#pragma unroll
    for (int mi = 0; mi < 4; mi++)
#pragma unroll
        for (int ni = 0; ni < 4; ni++) {
            int r = wm * 64 + mi * 16 + (lane >> 2);
            int cbase = wn * 32 + ni * 8 + (lane & 3) * 2;
            Cst[r * 132 + cbase]           = acc[mi][ni][0];
            Cst[r * 132 + cbase + 1]       = acc[mi][ni][1];
            Cst[(r + 8) * 132 + cbase]     = acc[mi][ni][2];
            Cst[(r + 8) * 132 + cbase + 1] = acc[mi][ni][3];
        }
    __syncthreads();

    for (int it = tid; it < 128 * 32; it += 256) {
        int row = it >> 5;
        int col = (it & 31) * 4;
        int m = m0 + row;
        if (mode == 1 && m >= Mact) continue;
        float4 v = *(float4*)&Cst[row * 132 + col];
        float4 b1 = *(const float4*)(bias1 + n0 + col);
        v.x += b1.x; v.y += b1.y; v.z += b1.z; v.w += b1.w;
        float* dst;
        if (mode == 0) {
            float4 b2 = *(const float4*)(bias2 + n0 + col);
            v.x += b2.x; v.y += b2.y; v.z += b2.z; v.w += b2.w;
            dst = outp + (size_t)m * NG + n0 + col;
        } else {
            dst = outp + rowout[m] + n0 + col;
        }
        *(float4*)dst = v;
    }
}

// ---------------- step 0 ----------------
__global__ void __launch_bounds__(256) k_step0()
{
    int g = blockIdx.x * 256 + threadIdx.x;
    int b = g >> 10, d = g & 1023;
    const float* gx = d_gatesx + (long long)b * NG;
    float gi = gx[d];
    float gg = gx[2 * DDIM + d];
    float go = gx[3 * DDIM + d];
    float c = sigmf(gi) * tanhf(gg);
    float h = sigmf(go) * tanhf(c);
    d_c[g] = c;
    d_hbuf[0][g] = h;
}

// ---------------- recurrent step (software pipelined) ----------------
__global__ void __launch_bounds__(256) k_step(int s, const float* __restrict__ Whh)
{
    __shared__ float Hs[16][64];
    __shared__ float Ws[16][32];
    __shared__ float Gs[64][32];

    int tid = threadIdx.x;
    int d0  = blockIdx.x * 8;
    int cnt = d_cnt[s - 1];
    int rs  = d_rowstart[s - 1];
    int rp  = (s - 1) & 1, wp = s & 1;
    const float* hin  = d_hbuf[rp];
    float*       hout = d_hbuf[wp];

    int tx = tid & 15, ty = tid >> 4;
    int lrH = tid >> 2, kqH = (tid & 3) * 4;
    bool skip = (ty * 4 >= cnt);
    bool wload = (tid < 128);
    int wr = tid >> 2, wkq = (tid & 3) * 4;
    int wrow = (wr >> 3) * DDIM + d0 + (wr & 7);

    float acc[4][2] = {};
    float4 hv = *(const float4*)(hin + (long long)lrH * DDIM + kqH);
    float4 wv = wload ? *(const float4*)(Whh + (long long)wrow * DDIM + wkq)
                      : make_float4(0.f, 0.f, 0.f, 0.f);

    for (int k0 = 0; k0 < DDIM; k0 += 16) {
        Hs[kqH + 0][lrH] = hv.x; Hs[kqH + 1][lrH] = hv.y;
        Hs[kqH + 2][lrH] = hv.z; Hs[kqH + 3][lrH] = hv.w;
        if (wload) {
            Ws[wkq + 0][wr] = wv.x; Ws[wkq + 1][wr] = wv.y;
            Ws[wkq + 2][wr] = wv.z; Ws[wkq + 3][wr] = wv.w;
        }
        __syncthreads();
        if (k0 + 16 < DDIM) {
            hv = *(const float4*)(hin + (long long)lrH * DDIM + k0 + 16 + kqH);
            if (wload) wv = *(const float4*)(Whh + (long long)wrow * DDIM + k0 + 16 + wkq);
        }
        if (!skip) {
#pragma unroll
            for (int k = 0; k < 16; k++) {
                float4 av = *(const float4*)&Hs[k][ty * 4];
                float2 bw = *(const float2*)&Ws[k][tx * 2];
                float ar[4] = {av.x, av.y, av.z, av.w};
#pragma unroll
                for (int i = 0; i < 4; i++) {
                    acc[i][0] += ar[i] * bw.x;
                    acc[i][1] += ar[i] * bw.y;
                }
            }
        }
        __syncthreads();
    }

    if (!skip) {
#pragma unroll
        for (int i = 0; i < 4; i++)
#pragma unroll
            for (int j = 0; j < 2; j++) {
                int row = ty * 4 + i;
                int col = tx * 2 + j;
                int gate = col >> 3, jj = col & 7;
                Gs[row][col] = acc[i][j] +
                    d_gatesx[((long long)s * BATCH + row) * NG + gate * DDIM + d0 + jj];
            }
    }
    __syncthreads();

    for (int it = tid; it < BATCH * 8; it += 256) {
        int b = it >> 3, j = it & 7;
        int hidx = b * DDIM + d0 + j;
        float hval;
        if (b < cnt) {
            float gi = Gs[b][j],      gf = Gs[b][8 + j];
            float gg = Gs[b][16 + j], go = Gs[b][24 + j];
            float cold = d_c[hidx];
            float cn = sigmf(gf) * cold + sigmf(gi) * tanhf(gg);
            float hn = sigmf(go) * tanhf(cn);
            d_c[hidx] = cn;
            hval = hn;
            __nv_bfloat16 hh = __float2bfloat16(hval);
            __nv_bfloat16 hl = __float2bfloat16(hval - __bfloat162float(hh));
            int col = d0 + j;
            int ch = col >> 6, kc = col & 63;
            size_t o = ((size_t)ch * MROWS + rs + b) * CROW + kc * 2;
            *(__nv_bfloat16*)(d_HchiC + o) = hh;
            *(__nv_bfloat16*)(d_HcloC + o) = hl;
        } else {
            hval = hin[hidx];
        }
        hout[hidx] = hval;
    }
}

// ---------------- launch ----------------
extern "C" void kernel_launch(void* const* d_in, const int* in_sizes, int n_in,
                              void* d_out, int out_size)
{
    const float* enc  = (const float*)d_in[0];
    const void*  caps = d_in[1];
    const void*  clen = d_in[2];
    const float* emb  = (const float*)d_in[3];
    const float* Wih  = (const float*)d_in[4];
    const float* Whh  = (const float*)d_in[5];
    const float* bih  = (const float*)d_in[6];
    const float* bhh  = (const float*)d_in[7];
    const float* fcW  = (const float*)d_in[8];
    const float* fcb  = (const float*)d_in[9];
    float* out = (float*)d_out;

    static int inited = 0;
    if (!inited) {
        cudaFuncSetAttribute(k_mma, cudaFuncAttributeMaxDynamicSharedMemorySize, SMEMB);
        inited = 1;
    }

    char *pXhiC, *pXloC, *pHchiC, *pHcloC, *pWihHiC, *pWihLoC, *pWfcHiC, *pWfcLoC;
    float* pGatesx;
    long long* pRowout;
    int *pMact, *pM2048;
    cudaGetSymbolAddress((void**)&pXhiC, d_XhiC);
    cudaGetSymbolAddress((void**)&pXloC, d_XloC);
    cudaGetSymbolAddress((void**)&pHchiC, d_HchiC);
    cudaGetSymbolAddress((void**)&pHcloC, d_HcloC);
    cudaGetSymbolAddress((void**)&pWihHiC, d_WihHiC);
    cudaGetSymbolAddress((void**)&pWihLoC, d_WihLoC);
    cudaGetSymbolAddress((void**)&pWfcHiC, d_WfcHiC);
    cudaGetSymbolAddress((void**)&pWfcLoC, d_WfcLoC);
    cudaGetSymbolAddress((void**)&pGatesx, d_gatesx);
    cudaGetSymbolAddress((void**)&pRowout, d_rowout);
    cudaGetSymbolAddress((void**)&pMact, d_Mact);
    cudaGetSymbolAddress((void**)&pM2048, d_M2048);

    // zero the full output (masked rows) and the compacted-H pads
    cudaMemsetAsync(out, 0, (size_t)out_size * sizeof(float));
    cudaMemsetAsync(pHchiC, 0, (size_t)NCHUNK * MROWS * CROW);
    cudaMemsetAsync(pHcloC, 0, (size_t)NCHUNK * MROWS * CROW);

    k_setup<<<1, 64>>>(clen, out, out_size);
    k_gather<<<TCAP * BATCH, 256>>>(enc, caps, emb);
    k_split<<<NG, 256>>>((const float4*)Wih, pWihHiC, pWihLoC, NG);
    k_split<<<VOCAB, 256>>>((const float4*)fcW, pWfcHiC, pWfcLoC, VOCAB);

    // gates_x = X @ Wih^T + bih + bhh   (M=2048, N=4096)
    k_mma<<<dim3(16, 32), 256, SMEMB>>>(pXhiC, pXloC, pWihHiC, pWihLoC,
                                        MROWS, NG, bih, bhh, pGatesx,
                                        nullptr, pM2048, 0);

    k_step0<<<(BATCH * DDIM) / 256, 256>>>();
    for (int s = 1; s <= TDEC; s++)
        k_step<<<128, 256>>>(s, Whh);

    // predictions = Hc @ fcW^T + fcb, scattered  (M=Mact compacted, N=32000)
    k_mma<<<dim3(16, 250), 256, SMEMB>>>(pHchiC, pHcloC, pWfcHiC, pWfcLoC,
                                         MROWS, VOCAB, fcb, nullptr, out,
                                         pRowout, pMact, 1);
}

// round 8
// speedup vs baseline: 4.2794x; 1.3855x over previous
#include <cuda_runtime.h>
#include <cuda_bf16.h>
#include <cstdint>

#define BATCH 64
#define TCAP  32
#define VOCAB 32000
#define EDIM  1024
#define DDIM  1024
#define TDEC  31
#define NG    4096
#define MROWS 2048
#define CROW  144
#define NCHUNK 16
#define KSPLIT 4
#define NTILES 32          // 4096 / 128

// ---------------- static scratch ----------------
__device__ int   d_sortind[BATCH];
__device__ int   d_declen[BATCH];
__device__ int   d_cnt[TDEC];
__device__ int   d_rowstart[TDEC];
__device__ int   d_Mact;
__device__ int   d_M2048 = 2048;
__device__ int   d_i64;
__device__ int   d_ncnt[NTILES];                 // fan-in counters (zero-init)
__device__ long long d_rowout[MROWS];
__device__ __align__(16) float d_gatesx[TCAP * BATCH * NG];   // gate-PACKED cols
__device__ __align__(16) float d_biasPk[NG];
__device__ __align__(16) float d_c[BATCH * DDIM];
__device__ __align__(16) float d_part[KSPLIT][BATCH][NG];     // 4 MB step partials
// chunked + padded bf16 operands: [chunk][row][144B]
__device__ __align__(16) char d_XhiC [NCHUNK * MROWS * CROW];
__device__ __align__(16) char d_XloC [NCHUNK * MROWS * CROW];
__device__ __align__(16) char d_HchiC[NCHUNK * MROWS * CROW];
__device__ __align__(16) char d_HcloC[NCHUNK * MROWS * CROW];
__device__ __align__(16) char d_WihHiC[NCHUNK * NG * CROW];   // gate-packed rows
__device__ __align__(16) char d_WihLoC[NCHUNK * NG * CROW];
__device__ __align__(16) char d_WhhHiC[NCHUNK * NG * CROW];   // gate-packed rows
__device__ __align__(16) char d_WhhLoC[NCHUNK * NG * CROW];
__device__ __align__(16) char d_WfcHiC[NCHUNK * VOCAB * CROW];
__device__ __align__(16) char d_WfcLoC[NCHUNK * VOCAB * CROW];
// ping-pong h (bf16 hi/lo), chunked [2][chunk][64][144B]
__device__ __align__(16) char d_HpHi[2][NCHUNK * BATCH * CROW];
__device__ __align__(16) char d_HpLo[2][NCHUNK * BATCH * CROW];

__device__ __forceinline__ float sigmf(float x) { return 1.0f / (1.0f + expf(-x)); }

__device__ __forceinline__ uint32_t smem_u32(const void* p) {
    uint32_t a;
    asm("{ .reg .u64 t; cvta.to.shared.u64 t, %1; cvt.u32.u64 %0, t; }" : "=r"(a) : "l"(p));
    return a;
}

#define LDSM4(r0, r1, r2, r3, a) \
    asm volatile("ldmatrix.sync.aligned.m8n8.x4.shared.b16 {%0,%1,%2,%3}, [%4];" \
                 : "=r"(r0), "=r"(r1), "=r"(r2), "=r"(r3) : "r"(a))
#define LDSM2(r0, r1, a) \
    asm volatile("ldmatrix.sync.aligned.m8n8.x2.shared.b16 {%0,%1}, [%2];" \
                 : "=r"(r0), "=r"(r1) : "r"(a))
#define MMA16816(c, a, b) \
    asm volatile("mma.sync.aligned.m16n8k16.row.col.f32.bf16.bf16.f32 " \
                 "{%0,%1,%2,%3}, {%4,%5,%6,%7}, {%8,%9}, {%0,%1,%2,%3};" \
                 : "+f"((c)[0]), "+f"((c)[1]), "+f"((c)[2]), "+f"((c)[3]) \
                 : "r"((a)[0]), "r"((a)[1]), "r"((a)[2]), "r"((a)[3]), "r"((b)[0]), "r"((b)[1]))
#define MBAR_INIT(a, c)  asm volatile("mbarrier.init.shared.b64 [%0], %1;" :: "r"(a), "r"(c) : "memory")
#define MBAR_EXPECT(a, tx) asm volatile("mbarrier.arrive.expect_tx.shared.b64 _, [%0], %1;" :: "r"(a), "r"(tx) : "memory")
#define FENCE_ASYNC()    asm volatile("fence.proxy.async.shared::cta;" ::: "memory")
#define BULKCP(dst, src, sz, mb) \
    asm volatile("cp.async.bulk.shared::cluster.global.mbarrier::complete_tx::bytes [%0], [%1], %2, [%3];" \
                 :: "r"(dst), "l"(src), "r"(sz), "r"(mb) : "memory")

__device__ __forceinline__ void mbar_wait(uint32_t mb, uint32_t parity) {
    asm volatile(
        "{\n\t.reg .pred P;\n\t"
        "W%=:\n\t"
        "mbarrier.try_wait.parity.acquire.cta.shared::cta.b64 P, [%0], %1, 0x989680;\n\t"
        "@P bra.uni D%=;\n\t"
        "bra.uni W%=;\n\t"
        "D%=:\n\t}" :: "r"(mb), "r"(parity) : "memory");
}

// ---------------- setup ----------------
__global__ void k_setup(const void* __restrict__ cap_len_raw)
{
    __shared__ int len[BATCH];
    const int* p32 = (const int*)cap_len_raw;
    int is64 = (p32[1] == 0) ? 1 : 0;   // lengths in [2,32]; int64 high word == 0
    int i = threadIdx.x;
    if (i == 0) d_i64 = is64;
    if (i < BATCH) len[i] = p32[i << is64];
    __syncthreads();
    if (i < BATCH) {
        int li = len[i], r = 0;
        for (int j = 0; j < BATCH; j++) {
            int lj = len[j];
            if (lj > li || (lj == li && j < i)) r++;
        }
        d_sortind[r] = i;
        d_declen[r]  = li - 1;
    }
    __syncthreads();
    if (i < TDEC) {
        int c = 0;
        for (int b = 0; b < BATCH; b++)
            if (d_declen[b] > i) c++;
        d_cnt[i] = c;
    }
    __syncthreads();
    if (i == 0) {
        int acc = 0;
        for (int s = 0; s < TDEC; s++) { d_rowstart[s] = acc; acc += d_cnt[s]; }
        d_Mact = acc;
    }
    __syncthreads();
    for (int s = 0; s < TDEC; s++)
        if (i < d_cnt[s])
            d_rowout[d_rowstart[s] + i] = ((long long)i * TDEC + s) * VOCAB;
}

// tail of output (after the memset on the side stream has joined)
__global__ void k_tail(float* __restrict__ out, int out_size)
{
    int i = threadIdx.x;
    long long base = (long long)BATCH * TDEC * VOCAB;
    if (out_size >= (int)(base + 2 * BATCH) && i < BATCH) {
        out[base + i]         = (float)d_declen[i];
        out[base + BATCH + i] = (float)d_sortind[i];
    }
}

__global__ void k_packbias(const float* __restrict__ bih, const float* __restrict__ bhh)
{
    int p = blockIdx.x * 256 + threadIdx.x;      // packed col
    int o = (p & 3) * 1024 + (p >> 2);
    d_biasPk[p] = bih[o] + bhh[o];
}

// ---------------- gather: X as bf16 hi/lo into chunked layout ----------------
__global__ void __launch_bounds__(256) k_gather(const float* __restrict__ enc,
                                                const void* __restrict__ caps_raw,
                                                const float* __restrict__ emb)
{
    int row = blockIdx.x;          // t*BATCH + b
    int t = row >> 6, b = row & 63;
    int sb = d_sortind[b];
    const float* src;
    if (t == 0) {
        src = enc + (long long)sb * EDIM;
    } else {
        int idx = sb * TCAP + (t - 1);
        int tok = ((const int*)caps_raw)[idx << d_i64];
        src = emb + (long long)tok * EDIM;
    }
    float4 v = ((const float4*)src)[threadIdx.x];
    __nv_bfloat16 hx = __float2bfloat16(v.x), hy = __float2bfloat16(v.y);
    __nv_bfloat16 hz = __float2bfloat16(v.z), hw = __float2bfloat16(v.w);
    __nv_bfloat162 hA; hA.x = hx; hA.y = hy;
    __nv_bfloat162 hB; hB.x = hz; hB.y = hw;
    __nv_bfloat162 lA, lB;
    lA.x = __float2bfloat16(v.x - __bfloat162float(hx));
    lA.y = __float2bfloat16(v.y - __bfloat162float(hy));
    lB.x = __float2bfloat16(v.z - __bfloat162float(hz));
    lB.y = __float2bfloat16(v.w - __bfloat162float(hw));
    int col = threadIdx.x * 4;
    int ch = col >> 6, kc = col & 63;
    size_t off = ((size_t)ch * MROWS + row) * CROW + kc * 2;
    *(__nv_bfloat162*)(d_XhiC + off)     = hA;
    *(__nv_bfloat162*)(d_XhiC + off + 4) = hB;
    *(__nv_bfloat162*)(d_XloC + off)     = lA;
    *(__nv_bfloat162*)(d_XloC + off + 4) = lB;
}

// ---------------- split weights f32 -> bf16 hi/lo chunked (optional gate-pack perm) ----------------
__global__ void __launch_bounds__(256) k_split(const float4* __restrict__ src,
                                               char* __restrict__ hiC,
                                               char* __restrict__ loC, int nrows, int perm)
{
    int r = blockIdx.x;
    int p = perm ? ((r & 1023) * 4 + (r >> 10)) : r;
    int tid = threadIdx.x;
    float4 v = src[(size_t)r * 256 + tid];
    __nv_bfloat16 hx = __float2bfloat16(v.x), hy = __float2bfloat16(v.y);
    __nv_bfloat16 hz = __float2bfloat16(v.z), hw = __float2bfloat16(v.w);
    __nv_bfloat162 hA; hA.x = hx; hA.y = hy;
    __nv_bfloat162 hB; hB.x = hz; hB.y = hw;
    __nv_bfloat162 lA, lB;
    lA.x = __float2bfloat16(v.x - __bfloat162float(hx));
    lA.y = __float2bfloat16(v.y - __bfloat162float(hy));
    lB.x = __float2bfloat16(v.z - __bfloat162float(hz));
    lB.y = __float2bfloat16(v.w - __bfloat162float(hw));
    int col = tid * 4;
    int ch = col >> 6, kc = col & 63;
    size_t off = ((size_t)ch * nrows + p) * CROW + kc * 2;
    *(__nv_bfloat162*)(hiC + off)     = hA;
    *(__nv_bfloat162*)(hiC + off + 4) = hB;
    *(__nv_bfloat162*)(loC + off)     = lA;
    *(__nv_bfloat162*)(loC + off + 4) = lB;
}

// ================= bulk-copy mma.sync GEMM (128x128) =================
#define OPB2   (128 * CROW)
#define STGB   (4 * OPB2)
#define NSTG   3
#define SMEMB  (128 + NSTG * STGB)

__global__ void __launch_bounds__(256, 1) k_mma(
    const char* __restrict__ AhiC, const char* __restrict__ AloC,
    const char* __restrict__ BhiC, const char* __restrict__ BloC,
    int arows, int brows,
    const float* __restrict__ bias1,
    float* __restrict__ outp, const long long* __restrict__ rowout,
    const int* __restrict__ pMact, int mode)
{
    extern __shared__ char smem[];
    int tid = threadIdx.x;
    int m0 = blockIdx.x * 128;
    int n0 = blockIdx.y * 128;
    int Mact = *pMact;
    if (m0 >= Mact) return;

    uint32_t sb  = smem_u32(smem);
    uint32_t stg = sb + 128;
    int wid = tid >> 5, lane = tid & 31;
    int wm = wid & 1, wn = wid >> 1;

    if (tid == 0) { MBAR_INIT(sb + 0, 1); MBAR_INIT(sb + 8, 1); MBAR_INIT(sb + 16, 1); }
    FENCE_ASYNC();
    __syncthreads();

    const char* srcs[4] = { AhiC, AloC, BhiC, BloC };

    auto issue = [&](int c, int slot) {
        uint32_t mb = sb + slot * 8;
        MBAR_EXPECT(mb, 4 * OPB2);
#pragma unroll
        for (int op = 0; op < 4; op++) {
            int nr = (op < 2) ? arows : brows;
            int t0 = (op < 2) ? m0 : n0;
            const char* src = srcs[op] + ((size_t)c * nr + t0) * CROW;
            BULKCP(stg + slot * STGB + op * OPB2, src, OPB2, mb);
        }
    };

    float acc[4][4][4];
#pragma unroll
    for (int a = 0; a < 4; a++)
#pragma unroll
        for (int b = 0; b < 4; b++)
#pragma unroll
            for (int q = 0; q < 4; q++) acc[a][b][q] = 0.f;

    if (tid == 0) { issue(0, 0); issue(1, 1); }
    int ph[3] = { 0, 0, 0 };

    for (int c = 0; c < NCHUNK; c++) {
        if (tid == 0 && c + 2 < NCHUNK) issue(c + 2, (c + 2) % 3);
        int st = c % 3;
        mbar_wait(sb + st * 8, ph[st]); ph[st] ^= 1;

        uint32_t sbuf = stg + st * STGB;
#pragma unroll
        for (int kk = 0; kk < 4; kk++) {
            uint32_t ah[4][4], al[4][4], bh[4][2], bl[4][2];
            uint32_t abase = sbuf + (wm * 64 + (lane & 15)) * CROW + (lane >> 4) * 16 + kk * 32;
#pragma unroll
            for (int mi = 0; mi < 4; mi++)
                LDSM4(ah[mi][0], ah[mi][1], ah[mi][2], ah[mi][3], abase + mi * 16 * CROW);
#pragma unroll
            for (int mi = 0; mi < 4; mi++)
                LDSM4(al[mi][0], al[mi][1], al[mi][2], al[mi][3], abase + OPB2 + mi * 16 * CROW);
            uint32_t bbase = sbuf + 2 * OPB2 + (wn * 32 + (lane & 7)) * CROW + ((lane >> 3) & 1) * 16 + kk * 32;
#pragma unroll
            for (int ni = 0; ni < 4; ni++)
                LDSM2(bh[ni][0], bh[ni][1], bbase + ni * 8 * CROW);
#pragma unroll
            for (int ni = 0; ni < 4; ni++)
                LDSM2(bl[ni][0], bl[ni][1], bbase + OPB2 + ni * 8 * CROW);
#pragma unroll
            for (int mi = 0; mi < 4; mi++)
#pragma unroll
                for (int ni = 0; ni < 4; ni++) {
                    MMA16816(acc[mi][ni], ah[mi], bh[ni]);
                    MMA16816(acc[mi][ni], al[mi], bh[ni]);
                    MMA16816(acc[mi][ni], ah[mi], bl[ni]);
                }
        }
        __syncthreads();
    }

    float* Cst = (float*)smem;           // 128 x 132
#pragma unroll
    for (int mi = 0; mi < 4; mi++)
#pragma unroll
        for (int ni = 0; ni < 4; ni++) {
            int r = wm * 64 + mi * 16 + (lane >> 2);
            int cbase = wn * 32 + ni * 8 + (lane & 3) * 2;
            Cst[r * 132 + cbase]           = acc[mi][ni][0];
            Cst[r * 132 + cbase + 1]       = acc[mi][ni][1];
            Cst[(r + 8) * 132 + cbase]     = acc[mi][ni][2];
            Cst[(r + 8) * 132 + cbase + 1] = acc[mi][ni][3];
        }
    __syncthreads();

    for (int it = tid; it < 128 * 32; it += 256) {
        int row = it >> 5;
        int col = (it & 31) * 4;
        int m = m0 + row;
        if (mode == 1 && m >= Mact) continue;
        float4 v = *(float4*)&Cst[row * 132 + col];
        float4 b1 = *(const float4*)(bias1 + n0 + col);
        v.x += b1.x; v.y += b1.y; v.z += b1.z; v.w += b1.w;
        float* dst;
        if (mode == 0) dst = outp + (size_t)m * NG + n0 + col;
        else           dst = outp + rowout[m] + n0 + col;
        *(float4*)dst = v;
    }
}

// ---------------- step 0: h0,c0 from gatesx rows 0..63 (packed cols) ----------------
__global__ void __launch_bounds__(256) k_step0()
{
    int b = blockIdx.x;
    for (int d = threadIdx.x; d < DDIM; d += 256) {
        float4 gx = *(const float4*)&d_gatesx[(size_t)b * NG + d * 4];
        float c = sigmf(gx.x) * tanhf(gx.z);
        float h = sigmf(gx.w) * tanhf(c);
        d_c[b * DDIM + d] = c;
        __nv_bfloat16 hh = __float2bfloat16(h);
        __nv_bfloat16 hl = __float2bfloat16(h - __bfloat162float(hh));
        int ch = d >> 6, kc = d & 63;
        size_t o = ((size_t)ch * BATCH + b) * CROW + kc * 2;
        *(__nv_bfloat16*)(d_HpHi[0] + o) = hh;
        *(__nv_bfloat16*)(d_HpLo[0] + o) = hl;
    }
}

// ---------------- fused recurrent step: split-K mma + fan-in reduce + pointwise ----------------
// grid (NTILES, KSPLIT); block tile 64x128, K=256 per CTA (chunks ks*4 .. ks*4+3)
#define SOPA 9216                     // 64 x 144
#define SOPB 18432                    // 128 x 144
#define SSTG (2 * SOPA + 2 * SOPB)    // 55296
#define SMEM_S (128 + 2 * SSTG)       // 110720

__global__ void __launch_bounds__(256, 1) k_stepf(int s)
{
    extern __shared__ char smem[];
    int tid = threadIdx.x;
    int nt = blockIdx.x, ks = blockIdx.y;
    int n0 = nt * 128;
    int rp = (s - 1) & 1, wp = s & 1;

    uint32_t sb  = smem_u32(smem);
    uint32_t stg = sb + 128;
    int wid = tid >> 5, lane = tid & 31;
    int wm = wid & 1, wn = wid >> 1;

    if (tid == 0) { MBAR_INIT(sb + 0, 1); MBAR_INIT(sb + 8, 1); }
    FENCE_ASYNC();
    __syncthreads();

    auto issue = [&](int cc, int slot) {
        uint32_t mb = sb + slot * 8;
        int cg = ks * 4 + cc;
        MBAR_EXPECT(mb, SSTG);
        uint32_t base = stg + slot * SSTG;
        BULKCP(base,                    d_HpHi[rp] + (size_t)cg * SOPA, SOPA, mb);
        BULKCP(base + SOPA,             d_HpLo[rp] + (size_t)cg * SOPA, SOPA, mb);
        BULKCP(base + 2 * SOPA,        d_WhhHiC + ((size_t)cg * NG + n0) * CROW, SOPB, mb);
        BULKCP(base + 2 * SOPA + SOPB, d_WhhLoC + ((size_t)cg * NG + n0) * CROW, SOPB, mb);
    };

    float acc[2][4][4];
#pragma unroll
    for (int a = 0; a < 2; a++)
#pragma unroll
        for (int b = 0; b < 4; b++)
#pragma unroll
            for (int q = 0; q < 4; q++) acc[a][b][q] = 0.f;

    if (tid == 0) { issue(0, 0); issue(1, 1); }
    int ph[2] = { 0, 0 };

    for (int c = 0; c < 4; c++) {
        int st = c & 1;
        mbar_wait(sb + st * 8, ph[st]); ph[st] ^= 1;
        uint32_t sbuf = stg + st * SSTG;
#pragma unroll
        for (int kk = 0; kk < 4; kk++) {
            uint32_t ah[2][4], al[2][4], bh[4][2], bl[4][2];
            uint32_t abase = sbuf + (wm * 32 + (lane & 15)) * CROW + (lane >> 4) * 16 + kk * 32;
#pragma unroll
            for (int mi = 0; mi < 2; mi++)
                LDSM4(ah[mi][0], ah[mi][1], ah[mi][2], ah[mi][3], abase + mi * 16 * CROW);
#pragma unroll
            for (int mi = 0; mi < 2; mi++)
                LDSM4(al[mi][0], al[mi][1], al[mi][2], al[mi][3], abase + SOPA + mi * 16 * CROW);
            uint32_t bbase = sbuf + 2 * SOPA + (wn * 32 + (lane & 7)) * CROW + ((lane >> 3) & 1) * 16 + kk * 32;
#pragma unroll
            for (int ni = 0; ni < 4; ni++)
                LDSM2(bh[ni][0], bh[ni][1], bbase + ni * 8 * CROW);
#pragma unroll
            for (int ni = 0; ni < 4; ni++)
                LDSM2(bl[ni][0], bl[ni][1], bbase + SOPB + ni * 8 * CROW);
#pragma unroll
            for (int mi = 0; mi < 2; mi++)
#pragma unroll
                for (int ni = 0; ni < 4; ni++) {
                    MMA16816(acc[mi][ni], ah[mi], bh[ni]);
                    MMA16816(acc[mi][ni], al[mi], bh[ni]);
                    MMA16816(acc[mi][ni], ah[mi], bl[ni]);
                }
        }
        __syncthreads();
        if (tid == 0 && c + 2 < 4) issue(c + 2, st);
    }

    // write fp32 partial
#pragma unroll
    for (int mi = 0; mi < 2; mi++)
#pragma unroll
        for (int ni = 0; ni < 4; ni++) {
            int r = wm * 32 + mi * 16 + (lane >> 2);
            int col = n0 + wn * 32 + ni * 8 + (lane & 3) * 2;
            *(float2*)&d_part[ks][r][col]     = make_float2(acc[mi][ni][0], acc[mi][ni][1]);
            *(float2*)&d_part[ks][r + 8][col] = make_float2(acc[mi][ni][2], acc[mi][ni][3]);
        }
    __threadfence();
    __syncthreads();

    __shared__ int s_old;
    if (tid == 0) s_old = atomicAdd(&d_ncnt[nt], 1);
    __syncthreads();
    if (s_old != KSPLIT - 1) return;
    __threadfence();

    // fan-in reduce + LSTM pointwise for dims nd0..nd0+31
    int cnt = d_cnt[s - 1];
    int rs  = d_rowstart[s - 1];
    int nd0 = n0 >> 2;
    for (int it = tid; it < BATCH * 32; it += 256) {
        int b = it >> 5, di = it & 31;
        int dim = nd0 + di;
        int ch = dim >> 6, kc = dim & 63;
        size_t hoff = ((size_t)ch * BATCH + b) * CROW + kc * 2;
        if (b < cnt) {
            float4 g = *(const float4*)&d_gatesx[((size_t)s * BATCH + b) * NG + dim * 4];
            float4 p0 = *(const float4*)&d_part[0][b][dim * 4];
            float4 p1 = *(const float4*)&d_part[1][b][dim * 4];
            float4 p2 = *(const float4*)&d_part[2][b][dim * 4];
            float4 p3 = *(const float4*)&d_part[3][b][dim * 4];
            float gi = g.x + p0.x + p1.x + p2.x + p3.x;
            float gf = g.y + p0.y + p1.y + p2.y + p3.y;
            float gg = g.z + p0.z + p1.z + p2.z + p3.z;
            float go = g.w + p0.w + p1.w + p2.w + p3.w;
            float cold = d_c[b * DDIM + dim];
            float cn = sigmf(gf) * cold + sigmf(gi) * tanhf(gg);
            float hn = sigmf(go) * tanhf(cn);
            d_c[b * DDIM + dim] = cn;
            __nv_bfloat16 hh = __float2bfloat16(hn);
            __nv_bfloat16 hl = __float2bfloat16(hn - __bfloat162float(hh));
            *(__nv_bfloat16*)(d_HpHi[wp] + hoff) = hh;
            *(__nv_bfloat16*)(d_HpLo[wp] + hoff) = hl;
            size_t co = ((size_t)ch * MROWS + rs + b) * CROW + kc * 2;
            *(__nv_bfloat16*)(d_HchiC + co) = hh;
            *(__nv_bfloat16*)(d_HcloC + co) = hl;
        } else {
            *(__nv_bfloat16*)(d_HpHi[wp] + hoff) = *(const __nv_bfloat16*)(d_HpHi[rp] + hoff);
            *(__nv_bfloat16*)(d_HpLo[wp] + hoff) = *(const __nv_bfloat16*)(d_HpLo[rp] + hoff);
        }
    }
    if (tid == 0) d_ncnt[nt] = 0;      // reset for next step
}

// ---------------- launch ----------------
extern "C" void kernel_launch(void* const* d_in, const int* in_sizes, int n_in,
                              void* d_out, int out_size)
{
    const float* enc  = (const float*)d_in[0];
    const void*  caps = d_in[1];
    const void*  clen = d_in[2];
    const float* emb  = (const float*)d_in[3];
    const float* Wih  = (const float*)d_in[4];
    const float* Whh  = (const float*)d_in[5];
    const float* bih  = (const float*)d_in[6];
    const float* bhh  = (const float*)d_in[7];
    const float* fcW  = (const float*)d_in[8];
    const float* fcb  = (const float*)d_in[9];
    float* out = (float*)d_out;

    static cudaStream_t s2 = nullptr;
    static cudaEvent_t ev0 = nullptr, ev1 = nullptr;
    if (!s2) {
        cudaFuncSetAttribute(k_mma,   cudaFuncAttributeMaxDynamicSharedMemorySize, SMEMB);
        cudaFuncSetAttribute(k_stepf, cudaFuncAttributeMaxDynamicSharedMemorySize, SMEM_S);
        cudaStreamCreateWithFlags(&s2, cudaStreamNonBlocking);
        cudaEventCreateWithFlags(&ev0, cudaEventDisableTiming);
        cudaEventCreateWithFlags(&ev1, cudaEventDisableTiming);
    }

    char *pXhiC, *pXloC, *pHchiC, *pHcloC, *pWihHiC, *pWihLoC, *pWhhHiC, *pWhhLoC, *pWfcHiC, *pWfcLoC;
    float *pGatesx, *pBiasPk;
    long long* pRowout;
    int *pMact, *pM2048;
    cudaGetSymbolAddress((void**)&pXhiC, d_XhiC);
    cudaGetSymbolAddress((void**)&pXloC, d_XloC);
    cudaGetSymbolAddress((void**)&pHchiC, d_HchiC);
    cudaGetSymbolAddress((void**)&pHcloC, d_HcloC);
    cudaGetSymbolAddress((void**)&pWihHiC, d_WihHiC);
    cudaGetSymbolAddress((void**)&pWihLoC, d_WihLoC);
    cudaGetSymbolAddress((void**)&pWhhHiC, d_WhhHiC);
    cudaGetSymbolAddress((void**)&pWhhLoC, d_WhhLoC);
    cudaGetSymbolAddress((void**)&pWfcHiC, d_WfcHiC);
    cudaGetSymbolAddress((void**)&pWfcLoC, d_WfcLoC);
    cudaGetSymbolAddress((void**)&pGatesx, d_gatesx);
    cudaGetSymbolAddress((void**)&pBiasPk, d_biasPk);
    cudaGetSymbolAddress((void**)&pRowout, d_rowout);
    cudaGetSymbolAddress((void**)&pMact, d_Mact);
    cudaGetSymbolAddress((void**)&pM2048, d_M2048);

    // side stream: output memset + fc weight split, overlapped with the step chain
    cudaEventRecord(ev0, 0);
    cudaStreamWaitEvent(s2, ev0, 0);
    cudaMemsetAsync(out, 0, (size_t)out_size * sizeof(float), s2);
    k_split<<<VOCAB, 256, 0, s2>>>((const float4*)fcW, pWfcHiC, pWfcLoC, VOCAB, 0);
    cudaEventRecord(ev1, s2);

    // main stream
    cudaMemsetAsync(pHchiC, 0, (size_t)NCHUNK * MROWS * CROW);
    cudaMemsetAsync(pHcloC, 0, (size_t)NCHUNK * MROWS * CROW);
    k_setup<<<1, 64>>>(clen);
    k_gather<<<TCAP * BATCH, 256>>>(enc, caps, emb);
    k_split<<<NG, 256>>>((const float4*)Wih, pWihHiC, pWihLoC, NG, 1);
    k_split<<<NG, 256>>>((const float4*)Whh, pWhhHiC, pWhhLoC, NG, 1);
    k_packbias<<<NG / 256, 256>>>(bih, bhh);

    // gates_x = X @ WihPk^T + biasPk   (M=2048, N=4096 packed)
    k_mma<<<dim3(16, 32), 256, SMEMB>>>(pXhiC, pXloC, pWihHiC, pWihLoC,
                                        MROWS, NG, pBiasPk, pGatesx,
                                        nullptr, pM2048, 0);

    k_step0<<<BATCH, 256>>>();
    for (int s = 1; s <= TDEC; s++)
        k_stepf<<<dim3(NTILES, KSPLIT), 256, SMEM_S>>>(s);

    cudaStreamWaitEvent(0, ev1, 0);
    k_tail<<<1, 64>>>(out, out_size);

    // predictions = Hc @ fcW^T + fcb, scattered  (M=Mact compacted, N=32000)
    k_mma<<<dim3(16, 250), 256, SMEMB>>>(pHchiC, pHcloC, pWfcHiC, pWfcLoC,
                                         MROWS, VOCAB, fcb, out,
                                         pRowout, pMact, 1);
}